// round 1
// baseline (speedup 1.0000x reference)
#include <cuda_runtime.h>
#include <math.h>

// ---------------- problem dims (fixed for this problem) ----------------
#define Bb 2
#define Ls 1024
#define Dd 2048
#define Mm 2048
#define Pp 8
#define Kc 4
#define Ns (Bb*Ls)          // 2048 token rows
#define PL (Pp+Ls)          // 1032 kv rows per batch
#define NCHUNK 64

// ---------------- scratch (device globals; no allocation allowed) ------
__device__ float g_tmp1[Ns*Mm];
__device__ float g_tmp2[Ns*Mm];
__device__ float g_q[Ns*Mm];
__device__ float g_k[Ns*Mm];
__device__ float g_v[Ns*Mm];
__device__ float g_err[Ns*Mm];
__device__ float g_mom[Mm*Mm];
__device__ float g_snap[Mm*Mm];
__device__ float g_ret[Ns*Mm];
__device__ float g_gate[Ns*Mm];
__device__ float g_kwp[Bb*PL*Mm];
__device__ float g_vwp[Bb*PL*Mm];
__device__ float g_scores[Bb*Ls*PL];
__device__ float g_part[Bb*NCHUNK*3];
__device__ float g_scal[3];

// ---------------- epilogues ----------------
#define EPI_NONE  0
#define EPI_SILU  1
#define EPI_RSUB  2   // C = aux - acc
#define EPI_SCALE 3   // C = acc * alpha
#define EPI_ADD   4   // C = acc + aux
#define EPI_GATE  5   // C = sigmoid(acc + bias[col]) * aux

__device__ __forceinline__ float sigmoidf_(float x) { return 1.0f / (1.0f + __expf(-x)); }

// ---------------- SGEMM: C[Md,Nd] = opA(A) * opB(B), fp32 -------------
// OPA=0: A row-major [Md,Kd]; OPA=1: A stored [Kd,Md] (transposed use)
// OPB=0: B row-major [Kd,Nd]; OPB=1: B stored [Nd,Kd] (B^T use)
#define BM 128
#define BN 128
#define BK 16

template<int OPA, int OPB>
__global__ void __launch_bounds__(256, 2) sgemm_kernel(
    const float* __restrict__ A, const float* __restrict__ B, float* __restrict__ C,
    int Md, int Nd, int Kd,
    long long strA, long long strB, long long strC,
    int epi, const float* __restrict__ aux, long long strAux,
    const float* __restrict__ bias, float alpha)
{
    __shared__ float As[BK][BM];
    __shared__ float Bs[BK][BN];

    const int bz = blockIdx.z;
    A += (long long)bz * strA;
    B += (long long)bz * strB;
    C += (long long)bz * strC;
    if (aux) aux += (long long)bz * strAux;

    const int t  = threadIdx.x;
    const int tx = t & 15;
    const int ty = t >> 4;
    const int m0 = blockIdx.y * BM;
    const int n0 = blockIdx.x * BN;

    float acc[8][8];
#pragma unroll
    for (int i = 0; i < 8; i++)
#pragma unroll
        for (int j = 0; j < 8; j++) acc[i][j] = 0.0f;

    for (int k0 = 0; k0 < Kd; k0 += BK) {
        // ---- load A tile into As[k][m] ----
#pragma unroll
        for (int i = 0; i < 8; i++) {
            int linear = i * 256 + t;
            int m, k;
            if (OPA == 0) { k = linear & 15; m = linear >> 4; }
            else          { m = linear & 127; k = linear >> 7; }
            float v = 0.0f;
            int gm = m0 + m, gk = k0 + k;
            if (gm < Md && gk < Kd) {
                if (OPA == 0) v = A[(long long)gm * Kd + gk];
                else          v = A[(long long)gk * Md + gm];
            }
            As[k][m] = v;
        }
        // ---- load B tile into Bs[k][n] ----
#pragma unroll
        for (int i = 0; i < 8; i++) {
            int linear = i * 256 + t;
            int n, k;
            if (OPB == 0) { n = linear & 127; k = linear >> 7; }
            else          { k = linear & 15;  n = linear >> 4; }
            float v = 0.0f;
            int gn = n0 + n, gk = k0 + k;
            if (gn < Nd && gk < Kd) {
                if (OPB == 0) v = B[(long long)gk * Nd + gn];
                else          v = B[(long long)gn * Kd + gk];
            }
            Bs[k][n] = v;
        }
        __syncthreads();

#pragma unroll
        for (int kk = 0; kk < BK; kk++) {
            float4 a0 = *(const float4*)&As[kk][ty * 4];
            float4 a1 = *(const float4*)&As[kk][64 + ty * 4];
            float4 b0 = *(const float4*)&Bs[kk][tx * 4];
            float4 b1 = *(const float4*)&Bs[kk][64 + tx * 4];
            float av[8] = {a0.x, a0.y, a0.z, a0.w, a1.x, a1.y, a1.z, a1.w};
            float bv[8] = {b0.x, b0.y, b0.z, b0.w, b1.x, b1.y, b1.z, b1.w};
#pragma unroll
            for (int i = 0; i < 8; i++)
#pragma unroll
                for (int j = 0; j < 8; j++) acc[i][j] = fmaf(av[i], bv[j], acc[i][j]);
        }
        __syncthreads();
    }

    // ---- epilogue ----
#pragma unroll
    for (int i = 0; i < 8; i++) {
        int row = m0 + ((i < 4) ? (ty * 4 + i) : (64 + ty * 4 + i - 4));
        if (row >= Md) continue;
#pragma unroll
        for (int j = 0; j < 8; j++) {
            int col = n0 + ((j < 4) ? (tx * 4 + j) : (64 + tx * 4 + j - 4));
            if (col >= Nd) continue;
            float v = acc[i][j];
            long long idx = (long long)row * Nd + col;
            switch (epi) {
                case EPI_SILU:  v = v * sigmoidf_(v); break;
                case EPI_RSUB:  v = aux[idx] - v; break;
                case EPI_SCALE: v = v * alpha; break;
                case EPI_ADD:   v = v + aux[idx]; break;
                case EPI_GATE:  v = sigmoidf_(v + bias[col]) * aux[idx]; break;
                default: break;
            }
            C[idx] = v;
        }
    }
}

// ---------------- depthwise causal conv (K=4) ----------------
__global__ void dwconv_kernel(const float* __restrict__ in, const float* __restrict__ w,
                              float* __restrict__ out)
{
    long long idx = (long long)blockIdx.x * blockDim.x + threadIdx.x;
    if (idx >= (long long)Ns * Mm) return;
    int c = (int)(idx % Mm);
    long long bl = idx / Mm;
    int l = (int)(bl % Ls);
    long long b = bl / Ls;
    float s = 0.0f;
#pragma unroll
    for (int j = 0; j < Kc; j++) {
        int li = l - (Kc - 1) + j;
        if (li >= 0) s = fmaf(w[c * Kc + j], in[((long long)b * Ls + li) * Mm + c], s);
    }
    out[idx] = s;
}

// ---------------- row L2 normalize in-place ----------------
__global__ void l2n_kernel(float* __restrict__ p, int cols)
{
    __shared__ float sh[256];
    long long base = (long long)blockIdx.x * cols;
    int t = threadIdx.x;
    float ss = 0.0f;
    for (int i = t; i < cols; i += 256) { float v = p[base + i]; ss = fmaf(v, v, ss); }
    sh[t] = ss; __syncthreads();
    for (int s = 128; s > 0; s >>= 1) { if (t < s) sh[t] += sh[t + s]; __syncthreads(); }
    float inv = 1.0f / (sqrtf(sh[0]) + 1e-6f);
    for (int i = t; i < cols; i += 256) p[base + i] *= inv;
}

// ---------------- build k_wp / v_wp (persistent tokens + stream) -------
__global__ void build_wp_kernel(const float* __restrict__ pk, const float* __restrict__ pv,
                                const float* __restrict__ k, const float* __restrict__ v,
                                float* __restrict__ kwp, float* __restrict__ vwp)
{
    __shared__ float sh[256];
    int r = blockIdx.x;                 // 0 .. Bb*PL-1
    int b = r / PL;
    int p = r % PL;
    int t = threadIdx.x;
    long long dst = (long long)r * Mm;
    if (p < Pp) {
        float ss = 0.0f;
        for (int i = t; i < Mm; i += 256) { float x = pk[p * Mm + i]; ss = fmaf(x, x, ss); }
        sh[t] = ss; __syncthreads();
        for (int s = 128; s > 0; s >>= 1) { if (t < s) sh[t] += sh[t + s]; __syncthreads(); }
        float inv = 1.0f / (sqrtf(sh[0]) + 1e-6f);
        for (int i = t; i < Mm; i += 256) {
            kwp[dst + i] = pk[p * Mm + i] * inv;
            vwp[dst + i] = pv[p * Mm + i];
        }
    } else {
        long long src = ((long long)b * Ls + (p - Pp)) * Mm;
        for (int i = t; i < Mm; i += 256) {
            kwp[dst + i] = k[src + i];
            vwp[dst + i] = v[src + i];
        }
    }
}

// ---------------- eta/theta/alpha scalar pipeline ----------------
__global__ void pool_partial_kernel(const float* __restrict__ x,
                                    const float* __restrict__ ew, const float* __restrict__ tw,
                                    const float* __restrict__ aw, float* __restrict__ part)
{
    __shared__ float sh[256];
    int blk = blockIdx.x;               // Bb*NCHUNK blocks
    int b  = blk / NCHUNK;
    int ch = blk % NCHUNK;
    int t = threadIdx.x;
    const int span = (Ls * Dd) / NCHUNK;
    long long base = (long long)b * Ls * Dd;
    float s0 = 0.0f, s1 = 0.0f, s2 = 0.0f;
    for (int i = ch * span + t; i < (ch + 1) * span; i += 256) {
        float xv = x[base + i];
        int d = i & (Dd - 1);
        s0 = fmaf(xv, ew[d], s0);
        s1 = fmaf(xv, tw[d], s1);
        s2 = fmaf(xv, aw[d], s2);
    }
    float vals[3] = {s0, s1, s2};
#pragma unroll
    for (int c = 0; c < 3; c++) {
        sh[t] = vals[c]; __syncthreads();
        for (int s = 128; s > 0; s >>= 1) { if (t < s) sh[t] += sh[t + s]; __syncthreads(); }
        if (t == 0) part[(long long)blk * 3 + c] = sh[0];
        __syncthreads();
    }
}

__global__ void pool_final_kernel(const float* __restrict__ part,
                                  const float* __restrict__ eb, const float* __restrict__ tb,
                                  const float* __restrict__ ab, float* __restrict__ scal)
{
    if (threadIdx.x != 0) return;
    float biases[3] = {eb[0], tb[0], ab[0]};
    for (int c = 0; c < 3; c++) {
        float acc = 0.0f;
        for (int b = 0; b < Bb; b++) {
            float s = 0.0f;
            for (int ch = 0; ch < NCHUNK; ch++) s += part[((long long)(b * NCHUNK + ch)) * 3 + c];
            acc += sigmoidf_(s / (float)Ls + biases[c]);
        }
        scal[c] = acc / (float)Bb;
    }
}

// ---------------- snapshot = (1-alpha)*mem + eta*sur + theta*mom -------
__global__ void snap_kernel(const float* __restrict__ mem, const float* __restrict__ sur,
                            const float* __restrict__ mom, const float* __restrict__ scal,
                            float* __restrict__ snap)
{
    long long idx = (long long)blockIdx.x * blockDim.x + threadIdx.x;
    if (idx >= (long long)Mm * Mm) return;
    float eta = scal[0], theta = scal[1], alpha = scal[2];
    snap[idx] = (1.0f - alpha) * mem[idx] + eta * sur[idx] + theta * mom[idx];
}

// ---------------- masked softmax over rows of scores -------------------
__global__ void softmax_kernel(float* __restrict__ s)
{
    __shared__ float sh[256];
    int row = blockIdx.x;               // b*Ls + l
    int l = row % Ls;
    int limit = Pp + l + 1;             // contiguous visible range
    float* p = s + (long long)row * PL;
    int t = threadIdx.x;

    float mx = -INFINITY;
    for (int i = t; i < limit; i += 256) mx = fmaxf(mx, p[i]);
    sh[t] = mx; __syncthreads();
    for (int st = 128; st > 0; st >>= 1) { if (t < st) sh[t] = fmaxf(sh[t], sh[t + st]); __syncthreads(); }
    mx = sh[0]; __syncthreads();

    float sum = 0.0f;
    for (int i = t; i < limit; i += 256) { float e = __expf(p[i] - mx); p[i] = e; sum += e; }
    sh[t] = sum; __syncthreads();
    for (int st = 128; st > 0; st >>= 1) { if (t < st) sh[t] += sh[t + st]; __syncthreads(); }
    float inv = 1.0f / sh[0];

    for (int i = t; i < limit; i += 256) p[i] *= inv;
    for (int i = limit + t; i < PL; i += 256) p[i] = 0.0f;
}

// ---------------- final RMSNorm (in-place on d_out) --------------------
__global__ void rmsnorm_kernel(float* __restrict__ out, const float* __restrict__ lnw)
{
    __shared__ float sh[256];
    long long base = (long long)blockIdx.x * Dd;
    int t = threadIdx.x;
    float ss = 0.0f;
    for (int i = t; i < Dd; i += 256) { float v = out[base + i]; ss = fmaf(v, v, ss); }
    sh[t] = ss; __syncthreads();
    for (int s = 128; s > 0; s >>= 1) { if (t < s) sh[t] += sh[t + s]; __syncthreads(); }
    float inv = rsqrtf(sh[0] / (float)Dd + 1e-6f);
    for (int i = t; i < Dd; i += 256) out[base + i] = out[base + i] * inv * lnw[i];
}

// ---------------- host-side GEMM dispatch ----------------
static void gemm(int opa, int opb,
                 const float* A, const float* B, float* C,
                 int Md, int Nd, int Kd,
                 long long sA, long long sB, long long sC, int batch,
                 int epi, const float* aux, long long sAux,
                 const float* bias, float alpha)
{
    dim3 grid((Nd + BN - 1) / BN, (Md + BM - 1) / BM, batch);
    if (opa == 0 && opb == 0)
        sgemm_kernel<0, 0><<<grid, 256>>>(A, B, C, Md, Nd, Kd, sA, sB, sC, epi, aux, sAux, bias, alpha);
    else if (opa == 0 && opb == 1)
        sgemm_kernel<0, 1><<<grid, 256>>>(A, B, C, Md, Nd, Kd, sA, sB, sC, epi, aux, sAux, bias, alpha);
    else
        sgemm_kernel<1, 0><<<grid, 256>>>(A, B, C, Md, Nd, Kd, sA, sB, sC, epi, aux, sAux, bias, alpha);
}

extern "C" void kernel_launch(void* const* d_in, const int* in_sizes, int n_in,
                              void* d_out, int out_size)
{
    const float* x  = (const float*)d_in[0];
    const float* Wq = (const float*)d_in[1];
    const float* Wk = (const float*)d_in[2];
    const float* Wv = (const float*)d_in[3];

    // resolve dw/pw ordering ambiguity from element counts (dw = Mm*Kc = 8192)
    const float *q_dw, *k_dw, *v_dw, *q_pw, *k_pw, *v_pw;
    if (in_sizes[5] == Mm * Kc) {       // dict order: q_dw,k_dw,v_dw,q_pw,k_pw,v_pw
        q_dw = (const float*)d_in[4]; k_dw = (const float*)d_in[5]; v_dw = (const float*)d_in[6];
        q_pw = (const float*)d_in[7]; k_pw = (const float*)d_in[8]; v_pw = (const float*)d_in[9];
    } else {                            // signature order: q_dw,q_pw,k_dw,k_pw,v_dw,v_pw
        q_dw = (const float*)d_in[4]; q_pw = (const float*)d_in[5];
        k_dw = (const float*)d_in[6]; k_pw = (const float*)d_in[7];
        v_dw = (const float*)d_in[8]; v_pw = (const float*)d_in[9];
    }
    const float* pk      = (const float*)d_in[10];
    const float* pv      = (const float*)d_in[11];
    const float* mlp_w1  = (const float*)d_in[12];
    const float* mlp_w2  = (const float*)d_in[13];
    const float* eta_w   = (const float*)d_in[14];
    const float* eta_b   = (const float*)d_in[15];
    const float* theta_w = (const float*)d_in[16];
    const float* theta_b = (const float*)d_in[17];
    const float* alpha_w = (const float*)d_in[18];
    const float* alpha_b = (const float*)d_in[19];
    const float* gate_w  = (const float*)d_in[20];
    const float* gate_b  = (const float*)d_in[21];
    const float* out_w   = (const float*)d_in[22];
    const float* ln_w    = (const float*)d_in[23];
    const float* mem_st  = (const float*)d_in[24];
    const float* sur_st  = (const float*)d_in[25];
    float* out = (float*)d_out;

    float *tmp1, *tmp2, *q, *k, *v, *err, *mom, *snap, *ret, *gat, *kwp, *vwp, *scores, *part, *scal;
    cudaGetSymbolAddress((void**)&tmp1, g_tmp1);
    cudaGetSymbolAddress((void**)&tmp2, g_tmp2);
    cudaGetSymbolAddress((void**)&q,    g_q);
    cudaGetSymbolAddress((void**)&k,    g_k);
    cudaGetSymbolAddress((void**)&v,    g_v);
    cudaGetSymbolAddress((void**)&err,  g_err);
    cudaGetSymbolAddress((void**)&mom,  g_mom);
    cudaGetSymbolAddress((void**)&snap, g_snap);
    cudaGetSymbolAddress((void**)&ret,  g_ret);
    cudaGetSymbolAddress((void**)&gat,  g_gate);
    cudaGetSymbolAddress((void**)&kwp,  g_kwp);
    cudaGetSymbolAddress((void**)&vwp,  g_vwp);
    cudaGetSymbolAddress((void**)&scores, g_scores);
    cudaGetSymbolAddress((void**)&part, g_part);
    cudaGetSymbolAddress((void**)&scal, g_scal);

    const int EW = Ns * Mm;

    // eta / theta / alpha scalars
    pool_partial_kernel<<<Bb * NCHUNK, 256>>>(x, eta_w, theta_w, alpha_w, part);
    pool_final_kernel<<<1, 32>>>(part, eta_b, theta_b, alpha_b, scal);

    // q branch: proj -> dw conv -> pw conv + SiLU
    gemm(0, 1, x, Wq, tmp1, Ns, Mm, Dd, 0, 0, 0, 1, EPI_NONE, nullptr, 0, nullptr, 0.f);
    dwconv_kernel<<<EW / 256, 256>>>(tmp1, q_dw, tmp2);
    gemm(0, 1, tmp2, q_pw, q, Ns, Mm, Mm, 0, 0, 0, 1, EPI_SILU, nullptr, 0, nullptr, 0.f);
    // k branch
    gemm(0, 1, x, Wk, tmp1, Ns, Mm, Dd, 0, 0, 0, 1, EPI_NONE, nullptr, 0, nullptr, 0.f);
    dwconv_kernel<<<EW / 256, 256>>>(tmp1, k_dw, tmp2);
    gemm(0, 1, tmp2, k_pw, k, Ns, Mm, Mm, 0, 0, 0, 1, EPI_SILU, nullptr, 0, nullptr, 0.f);
    // v branch
    gemm(0, 1, x, Wv, tmp1, Ns, Mm, Dd, 0, 0, 0, 1, EPI_NONE, nullptr, 0, nullptr, 0.f);
    dwconv_kernel<<<EW / 256, 256>>>(tmp1, v_dw, tmp2);
    gemm(0, 1, tmp2, v_pw, v, Ns, Mm, Mm, 0, 0, 0, 1, EPI_SILU, nullptr, 0, nullptr, 0.f);

    // normalize q, k
    l2n_kernel<<<Ns, 256>>>(q, Mm);
    l2n_kernel<<<Ns, 256>>>(k, Mm);

    // persistent-token concat buffers
    build_wp_kernel<<<Bb * PL, 256>>>(pk, pv, k, v, kwp, vwp);

    // err = v - k @ mem_state
    gemm(0, 0, k, mem_st, err, Ns, Mm, Mm, 0, 0, 0, 1, EPI_RSUB, v, 0, nullptr, 0.f);
    // momentary = k^T @ err / (B*L)
    gemm(1, 0, k, err, mom, Mm, Mm, Ns, 0, 0, 0, 1, EPI_SCALE, nullptr, 0, nullptr, 1.0f / (float)Ns);
    // snapshot
    snap_kernel<<<(Mm * Mm) / 256, 256>>>(mem_st, sur_st, mom, scal, snap);

    // retrieved = q @ snapshot + silu(q @ w1^T) @ w2^T
    gemm(0, 0, q, snap, ret, Ns, Mm, Mm, 0, 0, 0, 1, EPI_NONE, nullptr, 0, nullptr, 0.f);
    gemm(0, 1, q, mlp_w1, tmp1, Ns, Mm, Mm, 0, 0, 0, 1, EPI_SILU, nullptr, 0, nullptr, 0.f);
    gemm(0, 1, tmp1, mlp_w2, ret, Ns, Mm, Mm, 0, 0, 0, 1, EPI_ADD, ret, 0, nullptr, 0.f);

    // attention: scores = q @ k_wp^T / sqrt(M)  (batched over B)
    gemm(0, 1, q, kwp, scores, Ls, PL, Mm,
         (long long)Ls * Mm, (long long)PL * Mm, (long long)Ls * PL, Bb,
         EPI_SCALE, nullptr, 0, nullptr, rsqrtf((float)Mm));
    softmax_kernel<<<Bb * Ls, 256>>>(scores);
    // retrieved += attn @ v_wp
    gemm(0, 0, scores, vwp, ret, Ls, Mm, PL,
         (long long)Ls * PL, (long long)PL * Mm, (long long)Ls * Mm, Bb,
         EPI_ADD, ret, (long long)Ls * Mm, nullptr, 0.f);

    // gate*retrieved
    gemm(0, 1, ret, gate_w, gat, Ns, Mm, Mm, 0, 0, 0, 1, EPI_GATE, ret, 0, gate_b, 0.f);
    // out = x + (gate*retrieved) @ out_w^T
    gemm(0, 1, gat, out_w, out, Ns, Dd, Mm, 0, 0, 0, 1, EPI_ADD, x, 0, nullptr, 0.f);
    // RMSNorm * ln_w
    rmsnorm_kernel<<<Ns, 256>>>(out, ln_w);
}

// round 2
// speedup vs baseline: 2.8341x; 2.8341x over previous
#include <cuda_runtime.h>
#include <math.h>
#include <stdint.h>

// ---------------- problem dims (fixed) ----------------
#define Bb 2
#define Ls 1024
#define Dd 2048
#define Mm 2048
#define Pp 8
#define Kc 4
#define Ns (Bb*Ls)
#define PL (Pp+Ls)
#define NCHUNK 64

// ---------------- scratch ----------------
__device__ float g_tmp1[Ns*Mm];
__device__ float g_tmp2[Ns*Mm];
__device__ float g_q[Ns*Mm];
__device__ float g_k[Ns*Mm];
__device__ float g_v[Ns*Mm];
__device__ float g_err[Ns*Mm];
__device__ float g_mom[Mm*Mm];
__device__ float g_snap[Mm*Mm];
__device__ float g_ret[Ns*Mm];
__device__ float g_gate[Ns*Mm];
__device__ float g_kwp[Bb*PL*Mm];
__device__ float g_vwp[Bb*PL*Mm];
__device__ float g_scores[Bb*Ls*PL];
__device__ float g_part[Bb*NCHUNK*3];
__device__ float g_scal[3];

// ---------------- epilogues ----------------
#define EPI_NONE  0
#define EPI_SILU  1
#define EPI_RSUB  2
#define EPI_SCALE 3
#define EPI_ADD   4
#define EPI_GATE  5

__device__ __forceinline__ float sigmoidf_(float x) { return 1.0f / (1.0f + __expf(-x)); }

__device__ __forceinline__ uint32_t f2tf(float x) {
    uint32_t r;
    asm("cvt.rna.tf32.f32 %0, %1;" : "=r"(r) : "f"(x));
    return r;
}

__device__ __forceinline__ void mma_tf32(float* d, const uint32_t* a, const uint32_t* b) {
    asm volatile(
        "mma.sync.aligned.m16n8k8.row.col.f32.tf32.tf32.f32 "
        "{%0,%1,%2,%3},{%4,%5,%6,%7},{%8,%9},{%0,%1,%2,%3};\n"
        : "+f"(d[0]), "+f"(d[1]), "+f"(d[2]), "+f"(d[3])
        : "r"(a[0]), "r"(a[1]), "r"(a[2]), "r"(a[3]), "r"(b[0]), "r"(b[1]));
}

// ---------------- TF32 tensor-core GEMM ----------------
// C[Md,Nd] = opA(A) * opB(B)
// OPA=0: A [Md,Kd] row-major ; OPA=1: A stored [Kd,Md] (use A^T)
// OPB=0: B [Kd,Nd] row-major ; OPB=1: B stored [Nd,Kd] (use B^T)
#define BM 128
#define BN 128
#define BK 16
#define SK 20    // padded smem stride (floats); conflict-free for frag loads

template<int OPA, int OPB>
__global__ void __launch_bounds__(256) tgemm_kernel(
    const float* __restrict__ A, const float* __restrict__ B, float* __restrict__ C,
    int Md, int Nd, int Kd,
    long long strA, long long strB, long long strC,
    int epi, const float* __restrict__ aux, long long strAux,
    const float* __restrict__ bias, float alpha)
{
    __shared__ uint32_t As[2][BM * SK];
    __shared__ uint32_t Bs[2][BN * SK];

    const int bz = blockIdx.z;
    A += (long long)bz * strA;
    B += (long long)bz * strB;
    C += (long long)bz * strC;
    if (aux) aux += (long long)bz * strAux;

    const int t    = threadIdx.x;
    const int lane = t & 31;
    const int warp = t >> 5;
    const int wm   = warp & 3;       // 4 warps along M
    const int wn   = warp >> 2;      // 2 warps along N
    const int grp  = lane >> 2;
    const int qid  = lane & 3;
    const int m0   = blockIdx.y * BM;
    const int n0   = blockIdx.x * BN;

    float acc[2][8][4];
#pragma unroll
    for (int mi = 0; mi < 2; mi++)
#pragma unroll
        for (int ni = 0; ni < 8; ni++)
#pragma unroll
            for (int c = 0; c < 4; c++) acc[mi][ni][c] = 0.0f;

    const int nk = (Kd + BK - 1) / BK;

    float4 ra[2], rb[2];

    // ---- LDG helpers (inline via lambdas would bloat; do macros in-line) ----
    auto ldgA = [&](int k0, float4 (&v)[2]) {
#pragma unroll
        for (int r = 0; r < 2; r++) {
            int lin = r * 256 + t;
            float4 x = {0.f, 0.f, 0.f, 0.f};
            if (OPA == 0) {
                int m = lin >> 2, kq = lin & 3;
                int gm = m0 + m, gk = k0 + kq * 4;
                if (gm < Md && gk < Kd) x = *(const float4*)(A + (long long)gm * Kd + gk);
            } else {
                int k = lin >> 5, mq = lin & 31;
                int gm = m0 + mq * 4, gk = k0 + k;
                if (gk < Kd && gm < Md) x = *(const float4*)(A + (long long)gk * Md + gm);
            }
            v[r] = x;
        }
    };
    auto ldgB = [&](int k0, float4 (&v)[2]) {
#pragma unroll
        for (int r = 0; r < 2; r++) {
            int lin = r * 256 + t;
            float4 x = {0.f, 0.f, 0.f, 0.f};
            if (OPB == 1) {
                int n = lin >> 2, kq = lin & 3;
                int gn = n0 + n, gk = k0 + kq * 4;
                if (gn < Nd && gk < Kd) x = *(const float4*)(B + (long long)gn * Kd + gk);
            } else {
                int k = lin >> 5, nq = lin & 31;
                int gn = n0 + nq * 4, gk = k0 + k;
                if (gk < Kd && gn < Nd) x = *(const float4*)(B + (long long)gk * Nd + gn);
            }
            v[r] = x;
        }
    };
    auto stsA = [&](int s, const float4 (&v)[2]) {
#pragma unroll
        for (int r = 0; r < 2; r++) {
            int lin = r * 256 + t;
            if (OPA == 0) {
                int m = lin >> 2, kq = lin & 3;
                uint32_t* d = &As[s][m * SK + kq * 4];
                d[0] = f2tf(v[r].x); d[1] = f2tf(v[r].y); d[2] = f2tf(v[r].z); d[3] = f2tf(v[r].w);
            } else {
                int k = lin >> 5, mq = lin & 31;
                As[s][(mq * 4 + 0) * SK + k] = f2tf(v[r].x);
                As[s][(mq * 4 + 1) * SK + k] = f2tf(v[r].y);
                As[s][(mq * 4 + 2) * SK + k] = f2tf(v[r].z);
                As[s][(mq * 4 + 3) * SK + k] = f2tf(v[r].w);
            }
        }
    };
    auto stsB = [&](int s, const float4 (&v)[2]) {
#pragma unroll
        for (int r = 0; r < 2; r++) {
            int lin = r * 256 + t;
            if (OPB == 1) {
                int n = lin >> 2, kq = lin & 3;
                uint32_t* d = &Bs[s][n * SK + kq * 4];
                d[0] = f2tf(v[r].x); d[1] = f2tf(v[r].y); d[2] = f2tf(v[r].z); d[3] = f2tf(v[r].w);
            } else {
                int k = lin >> 5, nq = lin & 31;
                Bs[s][(nq * 4 + 0) * SK + k] = f2tf(v[r].x);
                Bs[s][(nq * 4 + 1) * SK + k] = f2tf(v[r].y);
                Bs[s][(nq * 4 + 2) * SK + k] = f2tf(v[r].z);
                Bs[s][(nq * 4 + 3) * SK + k] = f2tf(v[r].w);
            }
        }
    };

    // prologue: stage 0
    ldgA(0, ra); ldgB(0, rb);
    stsA(0, ra); stsB(0, rb);

    for (int kt = 0; kt < nk; kt++) {
        __syncthreads();
        const int s = kt & 1;
        if (kt + 1 < nk) { ldgA((kt + 1) * BK, ra); ldgB((kt + 1) * BK, rb); }

#pragma unroll
        for (int kk = 0; kk < BK; kk += 8) {
            uint32_t af[2][4], bf[8][2];
#pragma unroll
            for (int mi = 0; mi < 2; mi++) {
                int r = wm * 32 + mi * 16 + grp;
                af[mi][0] = As[s][r * SK + kk + qid];
                af[mi][1] = As[s][(r + 8) * SK + kk + qid];
                af[mi][2] = As[s][r * SK + kk + qid + 4];
                af[mi][3] = As[s][(r + 8) * SK + kk + qid + 4];
            }
#pragma unroll
            for (int ni = 0; ni < 8; ni++) {
                int n = wn * 64 + ni * 8 + grp;
                bf[ni][0] = Bs[s][n * SK + kk + qid];
                bf[ni][1] = Bs[s][n * SK + kk + qid + 4];
            }
#pragma unroll
            for (int mi = 0; mi < 2; mi++)
#pragma unroll
                for (int ni = 0; ni < 8; ni++)
                    mma_tf32(acc[mi][ni], af[mi], bf[ni]);
        }

        if (kt + 1 < nk) { stsA((kt + 1) & 1, ra); stsB((kt + 1) & 1, rb); }
    }

    // ---- epilogue (float2 stores; cols are even-aligned pairs) ----
#pragma unroll
    for (int mi = 0; mi < 2; mi++) {
#pragma unroll
        for (int half = 0; half < 2; half++) {
            int row = m0 + wm * 32 + mi * 16 + grp + half * 8;
            if (row >= Md) continue;
#pragma unroll
            for (int ni = 0; ni < 8; ni++) {
                int col = n0 + wn * 64 + ni * 8 + qid * 2;
                if (col >= Nd) continue;
                float v0 = acc[mi][ni][half * 2 + 0];
                float v1 = acc[mi][ni][half * 2 + 1];
                long long idx = (long long)row * Nd + col;
                switch (epi) {
                    case EPI_SILU:
                        v0 = v0 * sigmoidf_(v0); v1 = v1 * sigmoidf_(v1); break;
                    case EPI_RSUB: {
                        float2 a2 = *(const float2*)(aux + idx);
                        v0 = a2.x - v0; v1 = a2.y - v1; break; }
                    case EPI_SCALE:
                        v0 *= alpha; v1 *= alpha; break;
                    case EPI_ADD: {
                        float2 a2 = *(const float2*)(aux + idx);
                        v0 += a2.x; v1 += a2.y; break; }
                    case EPI_GATE: {
                        float2 a2 = *(const float2*)(aux + idx);
                        v0 = sigmoidf_(v0 + bias[col]) * a2.x;
                        v1 = sigmoidf_(v1 + bias[col + 1]) * a2.y; break; }
                    default: break;
                }
                float2 o; o.x = v0; o.y = v1;
                *(float2*)(C + idx) = o;
            }
        }
    }
}

// ---------------- depthwise causal conv (K=4) ----------------
__global__ void dwconv_kernel(const float* __restrict__ in, const float* __restrict__ w,
                              float* __restrict__ out)
{
    long long idx = (long long)blockIdx.x * blockDim.x + threadIdx.x;
    if (idx >= (long long)Ns * Mm) return;
    int c = (int)(idx % Mm);
    long long bl = idx / Mm;
    int l = (int)(bl % Ls);
    long long b = bl / Ls;
    float s = 0.0f;
#pragma unroll
    for (int j = 0; j < Kc; j++) {
        int li = l - (Kc - 1) + j;
        if (li >= 0) s = fmaf(w[c * Kc + j], in[((long long)b * Ls + li) * Mm + c], s);
    }
    out[idx] = s;
}

// ---------------- row L2 normalize in-place ----------------
__global__ void l2n_kernel(float* __restrict__ p, int cols)
{
    __shared__ float sh[256];
    long long base = (long long)blockIdx.x * cols;
    int t = threadIdx.x;
    float ss = 0.0f;
    for (int i = t; i < cols; i += 256) { float v = p[base + i]; ss = fmaf(v, v, ss); }
    sh[t] = ss; __syncthreads();
    for (int s = 128; s > 0; s >>= 1) { if (t < s) sh[t] += sh[t + s]; __syncthreads(); }
    float inv = 1.0f / (sqrtf(sh[0]) + 1e-6f);
    for (int i = t; i < cols; i += 256) p[base + i] *= inv;
}

// ---------------- build k_wp / v_wp ----------------
__global__ void build_wp_kernel(const float* __restrict__ pk, const float* __restrict__ pv,
                                const float* __restrict__ k, const float* __restrict__ v,
                                float* __restrict__ kwp, float* __restrict__ vwp)
{
    __shared__ float sh[256];
    int r = blockIdx.x;
    int b = r / PL;
    int p = r % PL;
    int t = threadIdx.x;
    long long dst = (long long)r * Mm;
    if (p < Pp) {
        float ss = 0.0f;
        for (int i = t; i < Mm; i += 256) { float x = pk[p * Mm + i]; ss = fmaf(x, x, ss); }
        sh[t] = ss; __syncthreads();
        for (int s = 128; s > 0; s >>= 1) { if (t < s) sh[t] += sh[t + s]; __syncthreads(); }
        float inv = 1.0f / (sqrtf(sh[0]) + 1e-6f);
        for (int i = t; i < Mm; i += 256) {
            kwp[dst + i] = pk[p * Mm + i] * inv;
            vwp[dst + i] = pv[p * Mm + i];
        }
    } else {
        long long src = ((long long)b * Ls + (p - Pp)) * Mm;
        for (int i = t; i < Mm; i += 256) {
            kwp[dst + i] = k[src + i];
            vwp[dst + i] = v[src + i];
        }
    }
}

// ---------------- eta/theta/alpha ----------------
__global__ void pool_partial_kernel(const float* __restrict__ x,
                                    const float* __restrict__ ew, const float* __restrict__ tw,
                                    const float* __restrict__ aw, float* __restrict__ part)
{
    __shared__ float sh[256];
    int blk = blockIdx.x;
    int b  = blk / NCHUNK;
    int ch = blk % NCHUNK;
    int t = threadIdx.x;
    const int span = (Ls * Dd) / NCHUNK;
    long long base = (long long)b * Ls * Dd;
    float s0 = 0.0f, s1 = 0.0f, s2 = 0.0f;
    for (int i = ch * span + t; i < (ch + 1) * span; i += 256) {
        float xv = x[base + i];
        int d = i & (Dd - 1);
        s0 = fmaf(xv, ew[d], s0);
        s1 = fmaf(xv, tw[d], s1);
        s2 = fmaf(xv, aw[d], s2);
    }
    float vals[3] = {s0, s1, s2};
#pragma unroll
    for (int c = 0; c < 3; c++) {
        sh[t] = vals[c]; __syncthreads();
        for (int s = 128; s > 0; s >>= 1) { if (t < s) sh[t] += sh[t + s]; __syncthreads(); }
        if (t == 0) part[(long long)blk * 3 + c] = sh[0];
        __syncthreads();
    }
}

__global__ void pool_final_kernel(const float* __restrict__ part,
                                  const float* __restrict__ eb, const float* __restrict__ tb,
                                  const float* __restrict__ ab, float* __restrict__ scal)
{
    if (threadIdx.x != 0) return;
    float biases[3] = {eb[0], tb[0], ab[0]};
    for (int c = 0; c < 3; c++) {
        float acc = 0.0f;
        for (int b = 0; b < Bb; b++) {
            float s = 0.0f;
            for (int ch = 0; ch < NCHUNK; ch++) s += part[((long long)(b * NCHUNK + ch)) * 3 + c];
            acc += sigmoidf_(s / (float)Ls + biases[c]);
        }
        scal[c] = acc / (float)Bb;
    }
}

// ---------------- snapshot ----------------
__global__ void snap_kernel(const float* __restrict__ mem, const float* __restrict__ sur,
                            const float* __restrict__ mom, const float* __restrict__ scal,
                            float* __restrict__ snap)
{
    long long idx = (long long)blockIdx.x * blockDim.x + threadIdx.x;
    if (idx >= (long long)Mm * Mm) return;
    float eta = scal[0], theta = scal[1], alpha = scal[2];
    snap[idx] = (1.0f - alpha) * mem[idx] + eta * sur[idx] + theta * mom[idx];
}

// ---------------- masked softmax ----------------
__global__ void softmax_kernel(float* __restrict__ s)
{
    __shared__ float sh[256];
    int row = blockIdx.x;
    int l = row % Ls;
    int limit = Pp + l + 1;
    float* p = s + (long long)row * PL;
    int t = threadIdx.x;

    float mx = -INFINITY;
    for (int i = t; i < limit; i += 256) mx = fmaxf(mx, p[i]);
    sh[t] = mx; __syncthreads();
    for (int st = 128; st > 0; st >>= 1) { if (t < st) sh[t] = fmaxf(sh[t], sh[t + st]); __syncthreads(); }
    mx = sh[0]; __syncthreads();

    float sum = 0.0f;
    for (int i = t; i < limit; i += 256) { float e = __expf(p[i] - mx); p[i] = e; sum += e; }
    sh[t] = sum; __syncthreads();
    for (int st = 128; st > 0; st >>= 1) { if (t < st) sh[t] += sh[t + st]; __syncthreads(); }
    float inv = 1.0f / sh[0];

    for (int i = t; i < limit; i += 256) p[i] *= inv;
    for (int i = limit + t; i < PL; i += 256) p[i] = 0.0f;
}

// ---------------- final RMSNorm ----------------
__global__ void rmsnorm_kernel(float* __restrict__ out, const float* __restrict__ lnw)
{
    __shared__ float sh[256];
    long long base = (long long)blockIdx.x * Dd;
    int t = threadIdx.x;
    float ss = 0.0f;
    for (int i = t; i < Dd; i += 256) { float v = out[base + i]; ss = fmaf(v, v, ss); }
    sh[t] = ss; __syncthreads();
    for (int s = 128; s > 0; s >>= 1) { if (t < s) sh[t] += sh[t + s]; __syncthreads(); }
    float inv = rsqrtf(sh[0] / (float)Dd + 1e-6f);
    for (int i = t; i < Dd; i += 256) out[base + i] = out[base + i] * inv * lnw[i];
}

// ---------------- host-side dispatch ----------------
static void gemm(int opa, int opb,
                 const float* A, const float* B, float* C,
                 int Md, int Nd, int Kd,
                 long long sA, long long sB, long long sC, int batch,
                 int epi, const float* aux, long long sAux,
                 const float* bias, float alpha)
{
    dim3 grid((Nd + BN - 1) / BN, (Md + BM - 1) / BM, batch);
    if (opa == 0 && opb == 0)
        tgemm_kernel<0, 0><<<grid, 256>>>(A, B, C, Md, Nd, Kd, sA, sB, sC, epi, aux, sAux, bias, alpha);
    else if (opa == 0 && opb == 1)
        tgemm_kernel<0, 1><<<grid, 256>>>(A, B, C, Md, Nd, Kd, sA, sB, sC, epi, aux, sAux, bias, alpha);
    else
        tgemm_kernel<1, 0><<<grid, 256>>>(A, B, C, Md, Nd, Kd, sA, sB, sC, epi, aux, sAux, bias, alpha);
}

extern "C" void kernel_launch(void* const* d_in, const int* in_sizes, int n_in,
                              void* d_out, int out_size)
{
    const float* x  = (const float*)d_in[0];
    const float* Wq = (const float*)d_in[1];
    const float* Wk = (const float*)d_in[2];
    const float* Wv = (const float*)d_in[3];

    const float *q_dw, *k_dw, *v_dw, *q_pw, *k_pw, *v_pw;
    if (in_sizes[5] == Mm * Kc) {
        q_dw = (const float*)d_in[4]; k_dw = (const float*)d_in[5]; v_dw = (const float*)d_in[6];
        q_pw = (const float*)d_in[7]; k_pw = (const float*)d_in[8]; v_pw = (const float*)d_in[9];
    } else {
        q_dw = (const float*)d_in[4]; q_pw = (const float*)d_in[5];
        k_dw = (const float*)d_in[6]; k_pw = (const float*)d_in[7];
        v_dw = (const float*)d_in[8]; v_pw = (const float*)d_in[9];
    }
    const float* pk      = (const float*)d_in[10];
    const float* pv      = (const float*)d_in[11];
    const float* mlp_w1  = (const float*)d_in[12];
    const float* mlp_w2  = (const float*)d_in[13];
    const float* eta_w   = (const float*)d_in[14];
    const float* eta_b   = (const float*)d_in[15];
    const float* theta_w = (const float*)d_in[16];
    const float* theta_b = (const float*)d_in[17];
    const float* alpha_w = (const float*)d_in[18];
    const float* alpha_b = (const float*)d_in[19];
    const float* gate_w  = (const float*)d_in[20];
    const float* gate_b  = (const float*)d_in[21];
    const float* out_w   = (const float*)d_in[22];
    const float* ln_w    = (const float*)d_in[23];
    const float* mem_st  = (const float*)d_in[24];
    const float* sur_st  = (const float*)d_in[25];
    float* out = (float*)d_out;

    float *tmp1, *tmp2, *q, *k, *v, *err, *mom, *snap, *ret, *gat, *kwp, *vwp, *scores, *part, *scal;
    cudaGetSymbolAddress((void**)&tmp1, g_tmp1);
    cudaGetSymbolAddress((void**)&tmp2, g_tmp2);
    cudaGetSymbolAddress((void**)&q,    g_q);
    cudaGetSymbolAddress((void**)&k,    g_k);
    cudaGetSymbolAddress((void**)&v,    g_v);
    cudaGetSymbolAddress((void**)&err,  g_err);
    cudaGetSymbolAddress((void**)&mom,  g_mom);
    cudaGetSymbolAddress((void**)&snap, g_snap);
    cudaGetSymbolAddress((void**)&ret,  g_ret);
    cudaGetSymbolAddress((void**)&gat,  g_gate);
    cudaGetSymbolAddress((void**)&kwp,  g_kwp);
    cudaGetSymbolAddress((void**)&vwp,  g_vwp);
    cudaGetSymbolAddress((void**)&scores, g_scores);
    cudaGetSymbolAddress((void**)&part, g_part);
    cudaGetSymbolAddress((void**)&scal, g_scal);

    const int EW = Ns * Mm;

    pool_partial_kernel<<<Bb * NCHUNK, 256>>>(x, eta_w, theta_w, alpha_w, part);
    pool_final_kernel<<<1, 32>>>(part, eta_b, theta_b, alpha_b, scal);

    // q branch
    gemm(0, 1, x, Wq, tmp1, Ns, Mm, Dd, 0, 0, 0, 1, EPI_NONE, nullptr, 0, nullptr, 0.f);
    dwconv_kernel<<<EW / 256, 256>>>(tmp1, q_dw, tmp2);
    gemm(0, 1, tmp2, q_pw, q, Ns, Mm, Mm, 0, 0, 0, 1, EPI_SILU, nullptr, 0, nullptr, 0.f);
    // k branch
    gemm(0, 1, x, Wk, tmp1, Ns, Mm, Dd, 0, 0, 0, 1, EPI_NONE, nullptr, 0, nullptr, 0.f);
    dwconv_kernel<<<EW / 256, 256>>>(tmp1, k_dw, tmp2);
    gemm(0, 1, tmp2, k_pw, k, Ns, Mm, Mm, 0, 0, 0, 1, EPI_SILU, nullptr, 0, nullptr, 0.f);
    // v branch
    gemm(0, 1, x, Wv, tmp1, Ns, Mm, Dd, 0, 0, 0, 1, EPI_NONE, nullptr, 0, nullptr, 0.f);
    dwconv_kernel<<<EW / 256, 256>>>(tmp1, v_dw, tmp2);
    gemm(0, 1, tmp2, v_pw, v, Ns, Mm, Mm, 0, 0, 0, 1, EPI_SILU, nullptr, 0, nullptr, 0.f);

    l2n_kernel<<<Ns, 256>>>(q, Mm);
    l2n_kernel<<<Ns, 256>>>(k, Mm);

    build_wp_kernel<<<Bb * PL, 256>>>(pk, pv, k, v, kwp, vwp);

    // err = v - k @ mem_state
    gemm(0, 0, k, mem_st, err, Ns, Mm, Mm, 0, 0, 0, 1, EPI_RSUB, v, 0, nullptr, 0.f);
    // momentary = k^T @ err / (B*L)
    gemm(1, 0, k, err, mom, Mm, Mm, Ns, 0, 0, 0, 1, EPI_SCALE, nullptr, 0, nullptr, 1.0f / (float)Ns);
    snap_kernel<<<(Mm * Mm) / 256, 256>>>(mem_st, sur_st, mom, scal, snap);

    // retrieved = q @ snapshot + silu(q @ w1^T) @ w2^T
    gemm(0, 0, q, snap, ret, Ns, Mm, Mm, 0, 0, 0, 1, EPI_NONE, nullptr, 0, nullptr, 0.f);
    gemm(0, 1, q, mlp_w1, tmp1, Ns, Mm, Mm, 0, 0, 0, 1, EPI_SILU, nullptr, 0, nullptr, 0.f);
    gemm(0, 1, tmp1, mlp_w2, ret, Ns, Mm, Mm, 0, 0, 0, 1, EPI_ADD, ret, 0, nullptr, 0.f);

    // attention
    gemm(0, 1, q, kwp, scores, Ls, PL, Mm,
         (long long)Ls * Mm, (long long)PL * Mm, (long long)Ls * PL, Bb,
         EPI_SCALE, nullptr, 0, nullptr, rsqrtf((float)Mm));
    softmax_kernel<<<Bb * Ls, 256>>>(scores);
    gemm(0, 0, scores, vwp, ret, Ls, Mm, PL,
         (long long)Ls * PL, (long long)PL * Mm, (long long)Ls * Mm, Bb,
         EPI_ADD, ret, (long long)Ls * Mm, nullptr, 0.f);

    // gate + output
    gemm(0, 1, ret, gate_w, gat, Ns, Mm, Mm, 0, 0, 0, 1, EPI_GATE, ret, 0, gate_b, 0.f);
    gemm(0, 1, gat, out_w, out, Ns, Dd, Mm, 0, 0, 0, 1, EPI_ADD, x, 0, nullptr, 0.f);
    rmsnorm_kernel<<<Ns, 256>>>(out, ln_w);
}

// round 4
// speedup vs baseline: 5.6323x; 1.9873x over previous
#include <cuda_runtime.h>
#include <cuda_bf16.h>
#include <math.h>
#include <stdint.h>

// ---------------- problem dims (fixed) ----------------
#define Bb 2
#define Ls 1024
#define Dd 2048
#define Mm 2048
#define Pp 8
#define Kc 4
#define Ns (Bb*Ls)
#define PL (Pp+Ls)
#define NCHUNK 64

// ---------------- scratch ----------------
__device__ float g_tmp1[Ns*Mm];
__device__ float g_tmp2[Ns*Mm];
__device__ float g_q[Ns*Mm];
__device__ float g_k[Ns*Mm];
__device__ float g_kT[Ns*Mm];
__device__ float g_v[Ns*Mm];
__device__ float g_err[Ns*Mm];
__device__ float g_errT[Ns*Mm];
__device__ float g_memT[Mm*Mm];
__device__ float g_mom[Mm*Mm];
__device__ float g_snapT[Mm*Mm];
__device__ float g_ret[Ns*Mm];
__device__ float g_gate[Ns*Mm];
__device__ float g_kwp[Bb*PL*Mm];
__device__ float g_vwp[Bb*PL*Mm];
__device__ float g_vwpT[Bb*Mm*PL];
__device__ float g_scores[Bb*Ls*PL];
__device__ float g_part[Bb*NCHUNK*3];
__device__ float g_scal[3];

// ---------------- epilogues ----------------
#define EPI_NONE  0
#define EPI_SILU  1
#define EPI_RSUB  2
#define EPI_SCALE 3
#define EPI_ADD   4
#define EPI_GATE  5

__device__ __forceinline__ float sigmoidf_(float x) { return 1.0f / (1.0f + __expf(-x)); }

__device__ __forceinline__ uint32_t pbf2(float lo, float hi) {
    uint32_t r;
    asm("cvt.rn.bf16x2.f32 %0, %1, %2;" : "=r"(r) : "f"(hi), "f"(lo));
    return r;
}

__device__ __forceinline__ void mma_bf16(float* d, const uint32_t* a, const uint32_t* b) {
    asm volatile(
        "mma.sync.aligned.m16n8k16.row.col.f32.bf16.bf16.f32 "
        "{%0,%1,%2,%3},{%4,%5,%6,%7},{%8,%9},{%0,%1,%2,%3};\n"
        : "+f"(d[0]), "+f"(d[1]), "+f"(d[2]), "+f"(d[3])
        : "r"(a[0]), "r"(a[1]), "r"(a[2]), "r"(a[3]), "r"(b[0]), "r"(b[1]));
}

// ---------------- bf16 tensor-core GEMM (NT): C[Md,Nd] = A[Md,Kd] * B^T, B stored [Nd,Kd]
#define BM 128
#define BN 128
#define BK 32
#define SKB 40     // padded smem row stride in bf16 units (20 words -> conflict-free)

__global__ void __launch_bounds__(256) bgemm_kernel(
    const float* __restrict__ A, const float* __restrict__ B, float* __restrict__ C,
    int Md, int Nd, int Kd,
    long long strA, long long strB, long long strC,
    int epi, const float* __restrict__ aux, long long strAux,
    const float* __restrict__ bias, float alpha)
{
    __shared__ __nv_bfloat16 As[2][BM * SKB];
    __shared__ __nv_bfloat16 Bs[2][BN * SKB];

    const int bz = blockIdx.z;
    A += (long long)bz * strA;
    B += (long long)bz * strB;
    C += (long long)bz * strC;
    if (aux) aux += (long long)bz * strAux;

    const int t    = threadIdx.x;
    const int lane = t & 31;
    const int warp = t >> 5;
    const int wm   = warp & 3;
    const int wn   = warp >> 2;
    const int grp  = lane >> 2;
    const int qid  = lane & 3;
    const int m0   = blockIdx.y * BM;
    const int n0   = blockIdx.x * BN;

    float acc[2][8][4];
#pragma unroll
    for (int mi = 0; mi < 2; mi++)
#pragma unroll
        for (int ni = 0; ni < 8; ni++)
#pragma unroll
            for (int c = 0; c < 4; c++) acc[mi][ni][c] = 0.0f;

    const int nk = (Kd + BK - 1) / BK;

    uint2 ra[4], rb[4];

    // 128 rows x 32 k per tile = 1024 float4 loads; 256 thr x 4 iters
    auto ldgA = [&](int k0) {
#pragma unroll
        for (int i = 0; i < 4; i++) {
            int lin = i * 256 + t;
            int m = lin >> 3, qd = lin & 7;
            int gm = m0 + m, gk = k0 + qd * 4;
            float4 x = make_float4(0.f, 0.f, 0.f, 0.f);
            if (gm < Md && gk + 3 < Kd) x = *(const float4*)(A + (long long)gm * Kd + gk);
            ra[i].x = pbf2(x.x, x.y);
            ra[i].y = pbf2(x.z, x.w);
        }
    };
    auto ldgB = [&](int k0) {
#pragma unroll
        for (int i = 0; i < 4; i++) {
            int lin = i * 256 + t;
            int n = lin >> 3, qd = lin & 7;
            int gn = n0 + n, gk = k0 + qd * 4;
            float4 x = make_float4(0.f, 0.f, 0.f, 0.f);
            if (gn < Nd && gk + 3 < Kd) x = *(const float4*)(B + (long long)gn * Kd + gk);
            rb[i].x = pbf2(x.x, x.y);
            rb[i].y = pbf2(x.z, x.w);
        }
    };
    auto stsA = [&](int s) {
#pragma unroll
        for (int i = 0; i < 4; i++) {
            int lin = i * 256 + t;
            int m = lin >> 3, qd = lin & 7;
            *(uint2*)&As[s][m * SKB + qd * 4] = ra[i];
        }
    };
    auto stsB = [&](int s) {
#pragma unroll
        for (int i = 0; i < 4; i++) {
            int lin = i * 256 + t;
            int n = lin >> 3, qd = lin & 7;
            *(uint2*)&Bs[s][n * SKB + qd * 4] = rb[i];
        }
    };

    ldgA(0); ldgB(0);
    stsA(0); stsB(0);

    for (int kt = 0; kt < nk; kt++) {
        __syncthreads();
        const int s = kt & 1;
        if (kt + 1 < nk) { ldgA((kt + 1) * BK); ldgB((kt + 1) * BK); }

#pragma unroll
        for (int kk = 0; kk < BK; kk += 16) {
            uint32_t af[2][4], bf[8][2];
#pragma unroll
            for (int mi = 0; mi < 2; mi++) {
                int r = wm * 32 + mi * 16 + grp;
                af[mi][0] = *(const uint32_t*)&As[s][r * SKB + kk + qid * 2];
                af[mi][1] = *(const uint32_t*)&As[s][(r + 8) * SKB + kk + qid * 2];
                af[mi][2] = *(const uint32_t*)&As[s][r * SKB + kk + qid * 2 + 8];
                af[mi][3] = *(const uint32_t*)&As[s][(r + 8) * SKB + kk + qid * 2 + 8];
            }
#pragma unroll
            for (int ni = 0; ni < 8; ni++) {
                int n = wn * 64 + ni * 8 + grp;
                bf[ni][0] = *(const uint32_t*)&Bs[s][n * SKB + kk + qid * 2];
                bf[ni][1] = *(const uint32_t*)&Bs[s][n * SKB + kk + qid * 2 + 8];
            }
#pragma unroll
            for (int mi = 0; mi < 2; mi++)
#pragma unroll
                for (int ni = 0; ni < 8; ni++)
                    mma_bf16(acc[mi][ni], af[mi], bf[ni]);
        }

        if (kt + 1 < nk) { stsA((kt + 1) & 1); stsB((kt + 1) & 1); }
    }

    // ---- epilogue (float2 stores; cols even-aligned) ----
#pragma unroll
    for (int mi = 0; mi < 2; mi++) {
#pragma unroll
        for (int half = 0; half < 2; half++) {
            int row = m0 + wm * 32 + mi * 16 + grp + half * 8;
            if (row >= Md) continue;
#pragma unroll
            for (int ni = 0; ni < 8; ni++) {
                int col = n0 + wn * 64 + ni * 8 + qid * 2;
                if (col + 1 >= Nd) continue;
                float v0 = acc[mi][ni][half * 2 + 0];
                float v1 = acc[mi][ni][half * 2 + 1];
                long long idx = (long long)row * Nd + col;
                switch (epi) {
                    case EPI_SILU:
                        v0 = v0 * sigmoidf_(v0); v1 = v1 * sigmoidf_(v1); break;
                    case EPI_RSUB: {
                        float2 a2 = *(const float2*)(aux + idx);
                        v0 = a2.x - v0; v1 = a2.y - v1; break; }
                    case EPI_SCALE:
                        v0 *= alpha; v1 *= alpha; break;
                    case EPI_ADD: {
                        float2 a2 = *(const float2*)(aux + idx);
                        v0 += a2.x; v1 += a2.y; break; }
                    case EPI_GATE: {
                        float2 a2 = *(const float2*)(aux + idx);
                        v0 = sigmoidf_(v0 + bias[col]) * a2.x;
                        v1 = sigmoidf_(v1 + bias[col + 1]) * a2.y; break; }
                    default: break;
                }
                float2 o; o.x = v0; o.y = v1;
                *(float2*)(C + idx) = o;
            }
        }
    }
}

// ---------------- tiled transpose ----------------
__global__ void transpose_kernel(const float* __restrict__ in, float* __restrict__ out,
                                 int R, int Cc, long long sIn, long long sOut)
{
    __shared__ float tile[32][33];
    int z = blockIdx.z;
    in  += (long long)z * sIn;
    out += (long long)z * sOut;
    int c0 = blockIdx.x * 32, r0 = blockIdx.y * 32;
    int tx = threadIdx.x, ty = threadIdx.y;
#pragma unroll
    for (int i = ty; i < 32; i += 8) {
        int r = r0 + i, c = c0 + tx;
        if (r < R && c < Cc) tile[i][tx] = in[(long long)r * Cc + c];
    }
    __syncthreads();
#pragma unroll
    for (int i = ty; i < 32; i += 8) {
        int c = c0 + i, r = r0 + tx;
        if (c < Cc && r < R) out[(long long)c * R + r] = tile[tx][i];
    }
}

// ---------------- snapT ----------------
__global__ void snapT_kernel(const float* __restrict__ mem, const float* __restrict__ sur,
                             const float* __restrict__ mom, const float* __restrict__ scal,
                             float* __restrict__ snapT)
{
    __shared__ float tile[32][33];
    int c0 = blockIdx.x * 32, r0 = blockIdx.y * 32;
    int tx = threadIdx.x, ty = threadIdx.y;
    float eta = scal[0], theta = scal[1], alpha = scal[2];
#pragma unroll
    for (int i = ty; i < 32; i += 8) {
        long long idx = (long long)(r0 + i) * Mm + c0 + tx;
        tile[i][tx] = (1.f - alpha) * mem[idx] + eta * sur[idx] + theta * mom[idx];
    }
    __syncthreads();
#pragma unroll
    for (int i = ty; i < 32; i += 8)
        snapT[(long long)(c0 + i) * Mm + r0 + tx] = tile[tx][i];
}

// ---------------- depthwise causal conv ----------------
__global__ void dwconv_kernel(const float* __restrict__ in, const float* __restrict__ w,
                              float* __restrict__ out)
{
    long long idx = (long long)blockIdx.x * blockDim.x + threadIdx.x;
    if (idx >= (long long)Ns * Mm) return;
    int c = (int)(idx % Mm);
    long long bl = idx / Mm;
    int l = (int)(bl % Ls);
    long long b = bl / Ls;
    float s = 0.0f;
#pragma unroll
    for (int j = 0; j < Kc; j++) {
        int li = l - (Kc - 1) + j;
        if (li >= 0) s = fmaf(w[c * Kc + j], in[((long long)b * Ls + li) * Mm + c], s);
    }
    out[idx] = s;
}

// ---------------- row L2 normalize ----------------
__global__ void l2n_kernel(float* __restrict__ p, int cols)
{
    __shared__ float sh[256];
    long long base = (long long)blockIdx.x * cols;
    int t = threadIdx.x;
    float ss = 0.0f;
    for (int i = t; i < cols; i += 256) { float v = p[base + i]; ss = fmaf(v, v, ss); }
    sh[t] = ss; __syncthreads();
    for (int s = 128; s > 0; s >>= 1) { if (t < s) sh[t] += sh[t + s]; __syncthreads(); }
    float inv = 1.0f / (sqrtf(sh[0]) + 1e-6f);
    for (int i = t; i < cols; i += 256) p[base + i] *= inv;
}

// ---------------- build k_wp / v_wp ----------------
__global__ void build_wp_kernel(const float* __restrict__ pk, const float* __restrict__ pv,
                                const float* __restrict__ k, const float* __restrict__ v,
                                float* __restrict__ kwp, float* __restrict__ vwp)
{
    __shared__ float sh[256];
    int r = blockIdx.x;
    int b = r / PL;
    int p = r % PL;
    int t = threadIdx.x;
    long long dst = (long long)r * Mm;
    if (p < Pp) {
        float ss = 0.0f;
        for (int i = t; i < Mm; i += 256) { float x = pk[p * Mm + i]; ss = fmaf(x, x, ss); }
        sh[t] = ss; __syncthreads();
        for (int s = 128; s > 0; s >>= 1) { if (t < s) sh[t] += sh[t + s]; __syncthreads(); }
        float inv = 1.0f / (sqrtf(sh[0]) + 1e-6f);
        for (int i = t; i < Mm; i += 256) {
            kwp[dst + i] = pk[p * Mm + i] * inv;
            vwp[dst + i] = pv[p * Mm + i];
        }
    } else {
        long long src = ((long long)b * Ls + (p - Pp)) * Mm;
        for (int i = t; i < Mm; i += 256) {
            kwp[dst + i] = k[src + i];
            vwp[dst + i] = v[src + i];
        }
    }
}

// ---------------- eta/theta/alpha ----------------
__global__ void pool_partial_kernel(const float* __restrict__ x,
                                    const float* __restrict__ ew, const float* __restrict__ tw,
                                    const float* __restrict__ aw, float* __restrict__ part)
{
    __shared__ float sh[256];
    int blk = blockIdx.x;
    int b  = blk / NCHUNK;
    int ch = blk % NCHUNK;
    int t = threadIdx.x;
    const int span = (Ls * Dd) / NCHUNK;
    long long base = (long long)b * Ls * Dd;
    float s0 = 0.0f, s1 = 0.0f, s2 = 0.0f;
    for (int i = ch * span + t; i < (ch + 1) * span; i += 256) {
        float xv = x[base + i];
        int d = i & (Dd - 1);
        s0 = fmaf(xv, ew[d], s0);
        s1 = fmaf(xv, tw[d], s1);
        s2 = fmaf(xv, aw[d], s2);
    }
    float vals[3] = {s0, s1, s2};
#pragma unroll
    for (int c = 0; c < 3; c++) {
        sh[t] = vals[c]; __syncthreads();
        for (int s = 128; s > 0; s >>= 1) { if (t < s) sh[t] += sh[t + s]; __syncthreads(); }
        if (t == 0) part[(long long)blk * 3 + c] = sh[0];
        __syncthreads();
    }
}

__global__ void pool_final_kernel(const float* __restrict__ part,
                                  const float* __restrict__ eb, const float* __restrict__ tb,
                                  const float* __restrict__ ab, float* __restrict__ scal)
{
    if (threadIdx.x != 0) return;
    float biases[3] = {eb[0], tb[0], ab[0]};
    for (int c = 0; c < 3; c++) {
        float acc = 0.0f;
        for (int b = 0; b < Bb; b++) {
            float s = 0.0f;
            for (int ch = 0; ch < NCHUNK; ch++) s += part[((long long)(b * NCHUNK + ch)) * 3 + c];
            acc += sigmoidf_(s / (float)Ls + biases[c]);
        }
        scal[c] = acc / (float)Bb;
    }
}

// ---------------- masked softmax ----------------
__global__ void softmax_kernel(float* __restrict__ s)
{
    __shared__ float sh[256];
    int row = blockIdx.x;
    int l = row % Ls;
    int limit = Pp + l + 1;
    float* p = s + (long long)row * PL;
    int t = threadIdx.x;

    float mx = -INFINITY;
    for (int i = t; i < limit; i += 256) mx = fmaxf(mx, p[i]);
    sh[t] = mx; __syncthreads();
    for (int st = 128; st > 0; st >>= 1) { if (t < st) sh[t] = fmaxf(sh[t], sh[t + st]); __syncthreads(); }
    mx = sh[0]; __syncthreads();

    float sum = 0.0f;
    for (int i = t; i < limit; i += 256) { float e = __expf(p[i] - mx); p[i] = e; sum += e; }
    sh[t] = sum; __syncthreads();
    for (int st = 128; st > 0; st >>= 1) { if (t < st) sh[t] += sh[t + st]; __syncthreads(); }
    float inv = 1.0f / sh[0];

    for (int i = t; i < limit; i += 256) p[i] *= inv;
    for (int i = limit + t; i < PL; i += 256) p[i] = 0.0f;
}

// ---------------- final RMSNorm ----------------
__global__ void rmsnorm_kernel(float* __restrict__ out, const float* __restrict__ lnw)
{
    __shared__ float sh[256];
    long long base = (long long)blockIdx.x * Dd;
    int t = threadIdx.x;
    float ss = 0.0f;
    for (int i = t; i < Dd; i += 256) { float v = out[base + i]; ss = fmaf(v, v, ss); }
    sh[t] = ss; __syncthreads();
    for (int s = 128; s > 0; s >>= 1) { if (t < s) sh[t] += sh[t + s]; __syncthreads(); }
    float inv = rsqrtf(sh[0] / (float)Dd + 1e-6f);
    for (int i = t; i < Dd; i += 256) out[base + i] = out[base + i] * inv * lnw[i];
}

// ---------------- host-side GEMM dispatch (NT only) ----------------
static void gemm(const float* A, const float* B, float* C,
                 int Md, int Nd, int Kd,
                 long long sA, long long sB, long long sC, int batch,
                 int epi, const float* aux, long long sAux,
                 const float* bias, float alpha)
{
    dim3 grid((Nd + BN - 1) / BN, (Md + BM - 1) / BM, batch);
    bgemm_kernel<<<grid, 256>>>(A, B, C, Md, Nd, Kd, sA, sB, sC, epi, aux, sAux, bias, alpha);
}

extern "C" void kernel_launch(void* const* d_in, const int* in_sizes, int n_in,
                              void* d_out, int out_size)
{
    const float* x  = (const float*)d_in[0];
    const float* Wq = (const float*)d_in[1];
    const float* Wk = (const float*)d_in[2];
    const float* Wv = (const float*)d_in[3];

    const float *q_dw, *k_dw, *v_dw, *q_pw, *k_pw, *v_pw;
    if (in_sizes[5] == Mm * Kc) {
        q_dw = (const float*)d_in[4]; k_dw = (const float*)d_in[5]; v_dw = (const float*)d_in[6];
        q_pw = (const float*)d_in[7]; k_pw = (const float*)d_in[8]; v_pw = (const float*)d_in[9];
    } else {
        q_dw = (const float*)d_in[4]; q_pw = (const float*)d_in[5];
        k_dw = (const float*)d_in[6]; k_pw = (const float*)d_in[7];
        v_dw = (const float*)d_in[8]; v_pw = (const float*)d_in[9];
    }
    const float* pk      = (const float*)d_in[10];
    const float* pv      = (const float*)d_in[11];
    const float* mlp_w1  = (const float*)d_in[12];
    const float* mlp_w2  = (const float*)d_in[13];
    const float* eta_w   = (const float*)d_in[14];
    const float* eta_b   = (const float*)d_in[15];
    const float* theta_w = (const float*)d_in[16];
    const float* theta_b = (const float*)d_in[17];
    const float* alpha_w = (const float*)d_in[18];
    const float* alpha_b = (const float*)d_in[19];
    const float* gate_w  = (const float*)d_in[20];
    const float* gate_b  = (const float*)d_in[21];
    const float* out_w   = (const float*)d_in[22];
    const float* ln_w    = (const float*)d_in[23];
    const float* mem_st  = (const float*)d_in[24];
    const float* sur_st  = (const float*)d_in[25];
    float* out = (float*)d_out;

    float *tmp1, *tmp2, *q, *k, *kT, *v, *err, *errT, *memT, *mom, *snapT, *ret, *gat;
    float *kwp, *vwp, *vwpT, *scores, *part, *scal;
    cudaGetSymbolAddress((void**)&tmp1, g_tmp1);
    cudaGetSymbolAddress((void**)&tmp2, g_tmp2);
    cudaGetSymbolAddress((void**)&q,    g_q);
    cudaGetSymbolAddress((void**)&k,    g_k);
    cudaGetSymbolAddress((void**)&kT,   g_kT);
    cudaGetSymbolAddress((void**)&v,    g_v);
    cudaGetSymbolAddress((void**)&err,  g_err);
    cudaGetSymbolAddress((void**)&errT, g_errT);
    cudaGetSymbolAddress((void**)&memT, g_memT);
    cudaGetSymbolAddress((void**)&mom,  g_mom);
    cudaGetSymbolAddress((void**)&snapT, g_snapT);
    cudaGetSymbolAddress((void**)&ret,  g_ret);
    cudaGetSymbolAddress((void**)&gat,  g_gate);
    cudaGetSymbolAddress((void**)&kwp,  g_kwp);
    cudaGetSymbolAddress((void**)&vwp,  g_vwp);
    cudaGetSymbolAddress((void**)&vwpT, g_vwpT);
    cudaGetSymbolAddress((void**)&scores, g_scores);
    cudaGetSymbolAddress((void**)&part, g_part);
    cudaGetSymbolAddress((void**)&scal, g_scal);

    const int EW = Ns * Mm;
    dim3 tb(32, 8);

    pool_partial_kernel<<<Bb * NCHUNK, 256>>>(x, eta_w, theta_w, alpha_w, part);
    pool_final_kernel<<<1, 32>>>(part, eta_b, theta_b, alpha_b, scal);

    // q/k/v branches
    gemm(x, Wq, tmp1, Ns, Mm, Dd, 0, 0, 0, 1, EPI_NONE, nullptr, 0, nullptr, 0.f);
    dwconv_kernel<<<EW / 256, 256>>>(tmp1, q_dw, tmp2);
    gemm(tmp2, q_pw, q, Ns, Mm, Mm, 0, 0, 0, 1, EPI_SILU, nullptr, 0, nullptr, 0.f);

    gemm(x, Wk, tmp1, Ns, Mm, Dd, 0, 0, 0, 1, EPI_NONE, nullptr, 0, nullptr, 0.f);
    dwconv_kernel<<<EW / 256, 256>>>(tmp1, k_dw, tmp2);
    gemm(tmp2, k_pw, k, Ns, Mm, Mm, 0, 0, 0, 1, EPI_SILU, nullptr, 0, nullptr, 0.f);

    gemm(x, Wv, tmp1, Ns, Mm, Dd, 0, 0, 0, 1, EPI_NONE, nullptr, 0, nullptr, 0.f);
    dwconv_kernel<<<EW / 256, 256>>>(tmp1, v_dw, tmp2);
    gemm(tmp2, v_pw, v, Ns, Mm, Mm, 0, 0, 0, 1, EPI_SILU, nullptr, 0, nullptr, 0.f);

    l2n_kernel<<<Ns, 256>>>(q, Mm);
    l2n_kernel<<<Ns, 256>>>(k, Mm);

    build_wp_kernel<<<Bb * PL, 256>>>(pk, pv, k, v, kwp, vwp);

    // err = v - k @ mem   (B = memT stored [Mm(out), Mm(k)] K-major)
    transpose_kernel<<<dim3(Mm / 32, Mm / 32, 1), tb>>>(mem_st, memT, Mm, Mm, 0, 0);
    gemm(k, memT, err, Ns, Mm, Mm, 0, 0, 0, 1, EPI_RSUB, v, 0, nullptr, 0.f);

    // momentary = k^T @ err / Ns   (A = kT [Mm,Ns], B = errT [Mm,Ns] K-major)
    transpose_kernel<<<dim3(Mm / 32, Ns / 32, 1), tb>>>(k, kT, Ns, Mm, 0, 0);
    transpose_kernel<<<dim3(Mm / 32, Ns / 32, 1), tb>>>(err, errT, Ns, Mm, 0, 0);
    gemm(kT, errT, mom, Mm, Mm, Ns, 0, 0, 0, 1, EPI_SCALE, nullptr, 0, nullptr, 1.0f / (float)Ns);

    snapT_kernel<<<dim3(Mm / 32, Mm / 32), tb>>>(mem_st, sur_st, mom, scal, snapT);

    // retrieved = q @ snap + silu(q @ w1^T) @ w2^T
    gemm(q, snapT, ret, Ns, Mm, Mm, 0, 0, 0, 1, EPI_NONE, nullptr, 0, nullptr, 0.f);
    gemm(q, mlp_w1, tmp1, Ns, Mm, Mm, 0, 0, 0, 1, EPI_SILU, nullptr, 0, nullptr, 0.f);
    gemm(tmp1, mlp_w2, ret, Ns, Mm, Mm, 0, 0, 0, 1, EPI_ADD, ret, 0, nullptr, 0.f);

    // attention
    gemm(q, kwp, scores, Ls, PL, Mm,
         (long long)Ls * Mm, (long long)PL * Mm, (long long)Ls * PL, Bb,
         EPI_SCALE, nullptr, 0, nullptr, rsqrtf((float)Mm));
    softmax_kernel<<<Bb * Ls, 256>>>(scores);
    transpose_kernel<<<dim3(Mm / 32, (PL + 31) / 32, Bb), tb>>>(vwp, vwpT, PL, Mm,
         (long long)PL * Mm, (long long)Mm * PL);
    gemm(scores, vwpT, ret, Ls, Mm, PL,
         (long long)Ls * PL, (long long)Mm * PL, (long long)Ls * Mm, Bb,
         EPI_ADD, ret, (long long)Ls * Mm, nullptr, 0.f);

    // gate + output + RMSNorm
    gemm(ret, gate_w, gat, Ns, Mm, Mm, 0, 0, 0, 1, EPI_GATE, ret, 0, gate_b, 0.f);
    gemm(gat, out_w, out, Ns, Dd, Mm, 0, 0, 0, 1, EPI_ADD, x, 0, nullptr, 0.f);
    rmsnorm_kernel<<<Ns, 256>>>(out, ln_w);
}

// round 5
// speedup vs baseline: 6.5188x; 1.1574x over previous
#include <cuda_runtime.h>
#include <cuda_bf16.h>
#include <math.h>
#include <stdint.h>

// ---------------- problem dims (fixed) ----------------
#define Bb 2
#define Ls 1024
#define Dd 2048
#define Mm 2048
#define Pp 8
#define Kc 4
#define Ns (Bb*Ls)
#define PL (Pp+Ls)
#define PLP 1056            // PL padded to multiple of 32
#define NCHUNK 64

typedef __nv_bfloat16 bf16;

// ---------------- fp32 scratch ----------------
__device__ float g_tmp1[Ns*Mm];
__device__ float g_q[Ns*Mm];
__device__ float g_k[Ns*Mm];
__device__ float g_v[Ns*Mm];
__device__ float g_err[Ns*Mm];
__device__ float g_mom[Mm*Mm];
__device__ float g_ret[Ns*Mm];
__device__ float g_vwp[Bb*PL*Mm];
__device__ float g_scores[Bb*Ls*PLP];
__device__ float g_part[Bb*NCHUNK*3];
__device__ float g_scal[3];

// ---------------- bf16 scratch ----------------
__device__ bf16 b_x[Ns*Dd];
__device__ bf16 b_Wq[Mm*Dd];
__device__ bf16 b_Wk[Mm*Dd];
__device__ bf16 b_Wv[Mm*Dd];
__device__ bf16 b_qpw[Mm*Mm];
__device__ bf16 b_kpw[Mm*Mm];
__device__ bf16 b_vpw[Mm*Mm];
__device__ bf16 b_w1[Mm*Mm];
__device__ bf16 b_w2[Mm*Mm];
__device__ bf16 b_gw[Mm*Mm];
__device__ bf16 b_ow[Dd*Mm];
__device__ bf16 b_tmp2[Ns*Mm];
__device__ bf16 b_q[Ns*Mm];
__device__ bf16 b_k[Ns*Mm];
__device__ bf16 b_kT[Mm*Ns];
__device__ bf16 b_errT[Mm*Ns];
__device__ bf16 b_memT[Mm*Mm];
__device__ bf16 b_snapT[Mm*Mm];
__device__ bf16 b_mlp[Ns*Mm];
__device__ bf16 b_kwp[Bb*PL*Mm];
__device__ bf16 b_vwpT[Bb*Mm*PLP];
__device__ bf16 b_scores[Bb*Ls*PLP];
__device__ bf16 b_ret[Ns*Mm];
__device__ bf16 b_gat[Ns*Mm];

// ---------------- epilogues ----------------
#define EPI_NONE  0
#define EPI_SILU  1
#define EPI_RSUB  2
#define EPI_SCALE 3
#define EPI_ADD   4
#define EPI_GATE  5

__device__ __forceinline__ float sigmoidf_(float x) { return 1.0f / (1.0f + __expf(-x)); }

__device__ __forceinline__ uint32_t pbf2(float lo, float hi) {
    uint32_t r;
    asm("cvt.rn.bf16x2.f32 %0, %1, %2;" : "=r"(r) : "f"(hi), "f"(lo));
    return r;
}

__device__ __forceinline__ uint32_t smem_u32(const void* p) {
    uint32_t a;
    asm("{ .reg .u64 t; cvta.to.shared.u64 t, %1; cvt.u32.u64 %0, t; }" : "=r"(a) : "l"(p));
    return a;
}

__device__ __forceinline__ void mma_bf16(float* d, const uint32_t* a, const uint32_t* b) {
    asm volatile(
        "mma.sync.aligned.m16n8k16.row.col.f32.bf16.bf16.f32 "
        "{%0,%1,%2,%3},{%4,%5,%6,%7},{%8,%9},{%0,%1,%2,%3};\n"
        : "+f"(d[0]), "+f"(d[1]), "+f"(d[2]), "+f"(d[3])
        : "r"(a[0]), "r"(a[1]), "r"(a[2]), "r"(a[3]), "r"(b[0]), "r"(b[1]));
}

__device__ __forceinline__ void cp16(uint32_t dst, const void* src, uint32_t sz) {
    asm volatile("cp.async.cg.shared.global [%0], [%1], 16, %2;"
                 :: "r"(dst), "l"(src), "r"(sz));
}

// ---------------- bf16 cp.async pipelined GEMM (NT) ----------------
// C[Md,Nd] = A[Md,Kd] * B^T ; A row-major (lda), B stored [Nd,Kd] (ldb).
// Requires: Md % 128 == 0, Kd % 32 == 0. Nd arbitrary (zero-filled edge).
#define BM 128
#define BN 128
#define BK 32
#define SKB 40               // padded smem row stride in bf16 elems (80B, 16B-aligned)
#define STAGES 4
#define TILE_ELEMS (BM * SKB)
#define SMEM_DYN (STAGES * 2 * TILE_ELEMS * 2)

__global__ void __launch_bounds__(256, 2) bgemm_kernel(
    const bf16* __restrict__ A, const bf16* __restrict__ B,
    float* __restrict__ C, bf16* __restrict__ Cb,
    int Md, int Nd, int Kd, int lda, int ldb, int ldc,
    long long strA, long long strB, long long strC,
    int epi, const float* __restrict__ aux, long long strAux,
    const float* __restrict__ bias, float alpha)
{
    extern __shared__ bf16 smp[];
    bf16* Asb = smp;
    bf16* Bsb = smp + STAGES * TILE_ELEMS;

    const int bz = blockIdx.z;
    A += (long long)bz * strA;
    B += (long long)bz * strB;
    if (C)   C  += (long long)bz * strC;
    if (Cb)  Cb += (long long)bz * strC;
    if (aux) aux += (long long)bz * strAux;

    const int t    = threadIdx.x;
    const int lane = t & 31;
    const int warp = t >> 5;
    const int wm   = warp & 3;
    const int wn   = warp >> 2;
    const int grp  = lane >> 2;
    const int qid  = lane & 3;
    const int m0   = blockIdx.y * BM;
    const int n0   = blockIdx.x * BN;

    float acc[2][8][4];
#pragma unroll
    for (int mi = 0; mi < 2; mi++)
#pragma unroll
        for (int ni = 0; ni < 8; ni++)
#pragma unroll
            for (int c = 0; c < 4; c++) acc[mi][ni][c] = 0.0f;

    const int nk = Kd / BK;

    // per-thread tile-chunk mapping: 512 chunks of 16B per operand, 2 per thread
    const int row0 = t >> 2;            // rows t/4 and t/4+64
    const int ch   = t & 3;             // 16B chunk within 64B row

    auto loadTile = [&](int stage, int k0) {
        uint32_t abase = smem_u32(&Asb[stage * TILE_ELEMS]);
        uint32_t bbase = smem_u32(&Bsb[stage * TILE_ELEMS]);
#pragma unroll
        for (int i = 0; i < 2; i++) {
            int m = row0 + i * 64;
            // A: rows always valid (Md % 128 == 0)
            cp16(abase + (m * SKB + ch * 8) * 2,
                 A + (long long)(m0 + m) * lda + k0 + ch * 8, 16u);
            int gn = n0 + m;
            bool ok = gn < Nd;
            cp16(bbase + (m * SKB + ch * 8) * 2,
                 B + (ok ? (long long)gn * ldb + k0 + ch * 8 : 0ll), ok ? 16u : 0u);
        }
        asm volatile("cp.async.commit_group;" ::: "memory");
    };

    // prologue: stages 0..2 (nk >= 33 always here)
    loadTile(0, 0);
    loadTile(1, BK);
    loadTile(2, 2 * BK);

    for (int kt = 0; kt < nk; kt++) {
        asm volatile("cp.async.wait_group 2;" ::: "memory");
        __syncthreads();

        // issue next tile into the stage freed by iter kt-1
        if (kt + 3 < nk) loadTile((kt + 3) & 3, (kt + 3) * BK);
        else asm volatile("cp.async.commit_group;" ::: "memory");

        const bf16* Ac = Asb + (kt & 3) * TILE_ELEMS;
        const bf16* Bc = Bsb + (kt & 3) * TILE_ELEMS;

#pragma unroll
        for (int kk = 0; kk < BK; kk += 16) {
            uint32_t af[2][4], bf[8][2];
#pragma unroll
            for (int mi = 0; mi < 2; mi++) {
                int r = wm * 32 + mi * 16 + grp;
                af[mi][0] = *(const uint32_t*)&Ac[r * SKB + kk + qid * 2];
                af[mi][1] = *(const uint32_t*)&Ac[(r + 8) * SKB + kk + qid * 2];
                af[mi][2] = *(const uint32_t*)&Ac[r * SKB + kk + qid * 2 + 8];
                af[mi][3] = *(const uint32_t*)&Ac[(r + 8) * SKB + kk + qid * 2 + 8];
            }
#pragma unroll
            for (int ni = 0; ni < 8; ni++) {
                int n = wn * 64 + ni * 8 + grp;
                bf[ni][0] = *(const uint32_t*)&Bc[n * SKB + kk + qid * 2];
                bf[ni][1] = *(const uint32_t*)&Bc[n * SKB + kk + qid * 2 + 8];
            }
#pragma unroll
            for (int mi = 0; mi < 2; mi++)
#pragma unroll
                for (int ni = 0; ni < 8; ni++)
                    mma_bf16(acc[mi][ni], af[mi], bf[ni]);
        }
    }

    // ---- epilogue ----
#pragma unroll
    for (int mi = 0; mi < 2; mi++) {
#pragma unroll
        for (int half = 0; half < 2; half++) {
            int row = m0 + wm * 32 + mi * 16 + grp + half * 8;
#pragma unroll
            for (int ni = 0; ni < 8; ni++) {
                int col = n0 + wn * 64 + ni * 8 + qid * 2;
                if (col + 1 >= Nd) continue;
                float v0 = acc[mi][ni][half * 2 + 0];
                float v1 = acc[mi][ni][half * 2 + 1];
                long long idx = (long long)row * ldc + col;
                switch (epi) {
                    case EPI_SILU:
                        v0 = v0 * sigmoidf_(v0); v1 = v1 * sigmoidf_(v1); break;
                    case EPI_RSUB: {
                        float2 a2 = *(const float2*)(aux + idx);
                        v0 = a2.x - v0; v1 = a2.y - v1; break; }
                    case EPI_SCALE:
                        v0 *= alpha; v1 *= alpha; break;
                    case EPI_ADD: {
                        float2 a2 = *(const float2*)(aux + idx);
                        v0 += a2.x; v1 += a2.y; break; }
                    case EPI_GATE: {
                        float2 a2 = *(const float2*)(aux + idx);
                        v0 = sigmoidf_(v0 + bias[col]) * a2.x;
                        v1 = sigmoidf_(v1 + bias[col + 1]) * a2.y; break; }
                    default: break;
                }
                if (C) { float2 o; o.x = v0; o.y = v1; *(float2*)(C + idx) = o; }
                if (Cb) *(uint32_t*)(Cb + idx) = pbf2(v0, v1);
            }
        }
    }
}

// ---------------- f32 -> bf16 convert ----------------
__global__ void cvt_kernel(const float4* __restrict__ in, uint2* __restrict__ out, int n4)
{
    int i = blockIdx.x * blockDim.x + threadIdx.x;
    if (i >= n4) return;
    float4 x = in[i];
    uint2 o; o.x = pbf2(x.x, x.y); o.y = pbf2(x.z, x.w);
    out[i] = o;
}

// ---------------- tiled transpose: f32 in -> bf16 out (zero-padded rows) ----
__global__ void transpose_bf_kernel(const float* __restrict__ in, bf16* __restrict__ out,
                                    int R, int Cc, int ldo, long long sIn, long long sOut)
{
    __shared__ float tile[32][33];
    int z = blockIdx.z;
    in  += (long long)z * sIn;
    out += (long long)z * sOut;
    int c0 = blockIdx.x * 32, r0 = blockIdx.y * 32;
    int tx = threadIdx.x, ty = threadIdx.y;
#pragma unroll
    for (int i = ty; i < 32; i += 8) {
        int r = r0 + i, c = c0 + tx;
        tile[i][tx] = (r < R && c < Cc) ? in[(long long)r * Cc + c] : 0.0f;
    }
    __syncthreads();
#pragma unroll
    for (int i = ty; i < 32; i += 8) {
        int c = c0 + i, r = r0 + tx;
        if (c < Cc && r < ldo) out[(long long)c * ldo + r] = __float2bfloat16(tile[tx][i]);
    }
}

// ---------------- snapT -> bf16 ----------------
__global__ void snapT_kernel(const float* __restrict__ mem, const float* __restrict__ sur,
                             const float* __restrict__ mom, const float* __restrict__ scal,
                             bf16* __restrict__ snapT)
{
    __shared__ float tile[32][33];
    int c0 = blockIdx.x * 32, r0 = blockIdx.y * 32;
    int tx = threadIdx.x, ty = threadIdx.y;
    float eta = scal[0], theta = scal[1], alpha = scal[2];
#pragma unroll
    for (int i = ty; i < 32; i += 8) {
        long long idx = (long long)(r0 + i) * Mm + c0 + tx;
        tile[i][tx] = (1.f - alpha) * mem[idx] + eta * sur[idx] + theta * mom[idx];
    }
    __syncthreads();
#pragma unroll
    for (int i = ty; i < 32; i += 8)
        snapT[(long long)(c0 + i) * Mm + r0 + tx] = __float2bfloat16(tile[tx][i]);
}

// ---------------- depthwise causal conv (bf16 out) ----------------
__global__ void dwconv_kernel(const float* __restrict__ in, const float* __restrict__ w,
                              bf16* __restrict__ out)
{
    long long idx = (long long)blockIdx.x * blockDim.x + threadIdx.x;
    if (idx >= (long long)Ns * Mm) return;
    int c = (int)(idx % Mm);
    long long bl = idx / Mm;
    int l = (int)(bl % Ls);
    long long b = bl / Ls;
    float s = 0.0f;
#pragma unroll
    for (int j = 0; j < Kc; j++) {
        int li = l - (Kc - 1) + j;
        if (li >= 0) s = fmaf(w[c * Kc + j], in[((long long)b * Ls + li) * Mm + c], s);
    }
    out[idx] = __float2bfloat16(s);
}

// ---------------- row L2 normalize (fp32 in-place + bf16 copy) ------
__global__ void l2n_kernel(float* __restrict__ p, bf16* __restrict__ pb, int cols)
{
    __shared__ float sh[256];
    long long base = (long long)blockIdx.x * cols;
    int t = threadIdx.x;
    float ss = 0.0f;
    for (int i = t; i < cols; i += 256) { float v = p[base + i]; ss = fmaf(v, v, ss); }
    sh[t] = ss; __syncthreads();
    for (int s = 128; s > 0; s >>= 1) { if (t < s) sh[t] += sh[t + s]; __syncthreads(); }
    float inv = 1.0f / (sqrtf(sh[0]) + 1e-6f);
    for (int i = t; i < cols; i += 256) {
        float v = p[base + i] * inv;
        p[base + i] = v;
        pb[base + i] = __float2bfloat16(v);
    }
}

// ---------------- build kwp (bf16) / vwp (fp32) ----------------
__global__ void build_wp_kernel(const float* __restrict__ pk, const float* __restrict__ pv,
                                const float* __restrict__ k, const float* __restrict__ v,
                                bf16* __restrict__ kwp, float* __restrict__ vwp)
{
    __shared__ float sh[256];
    int r = blockIdx.x;
    int b = r / PL;
    int p = r % PL;
    int t = threadIdx.x;
    long long dst = (long long)r * Mm;
    if (p < Pp) {
        float ss = 0.0f;
        for (int i = t; i < Mm; i += 256) { float x = pk[p * Mm + i]; ss = fmaf(x, x, ss); }
        sh[t] = ss; __syncthreads();
        for (int s = 128; s > 0; s >>= 1) { if (t < s) sh[t] += sh[t + s]; __syncthreads(); }
        float inv = 1.0f / (sqrtf(sh[0]) + 1e-6f);
        for (int i = t; i < Mm; i += 256) {
            kwp[dst + i] = __float2bfloat16(pk[p * Mm + i] * inv);
            vwp[dst + i] = pv[p * Mm + i];
        }
    } else {
        long long src = ((long long)b * Ls + (p - Pp)) * Mm;
        for (int i = t; i < Mm; i += 256) {
            kwp[dst + i] = __float2bfloat16(k[src + i]);
            vwp[dst + i] = v[src + i];
        }
    }
}

// ---------------- eta/theta/alpha ----------------
__global__ void pool_partial_kernel(const float* __restrict__ x,
                                    const float* __restrict__ ew, const float* __restrict__ tw,
                                    const float* __restrict__ aw, float* __restrict__ part)
{
    __shared__ float sh[256];
    int blk = blockIdx.x;
    int b  = blk / NCHUNK;
    int ch = blk % NCHUNK;
    int t = threadIdx.x;
    const int span = (Ls * Dd) / NCHUNK;
    long long base = (long long)b * Ls * Dd;
    float s0 = 0.0f, s1 = 0.0f, s2 = 0.0f;
    for (int i = ch * span + t; i < (ch + 1) * span; i += 256) {
        float xv = x[base + i];
        int d = i & (Dd - 1);
        s0 = fmaf(xv, ew[d], s0);
        s1 = fmaf(xv, tw[d], s1);
        s2 = fmaf(xv, aw[d], s2);
    }
    float vals[3] = {s0, s1, s2};
#pragma unroll
    for (int c = 0; c < 3; c++) {
        sh[t] = vals[c]; __syncthreads();
        for (int s = 128; s > 0; s >>= 1) { if (t < s) sh[t] += sh[t + s]; __syncthreads(); }
        if (t == 0) part[(long long)blk * 3 + c] = sh[0];
        __syncthreads();
    }
}

__global__ void pool_final_kernel(const float* __restrict__ part,
                                  const float* __restrict__ eb, const float* __restrict__ tb,
                                  const float* __restrict__ ab, float* __restrict__ scal)
{
    if (threadIdx.x != 0) return;
    float biases[3] = {eb[0], tb[0], ab[0]};
    for (int c = 0; c < 3; c++) {
        float acc = 0.0f;
        for (int b = 0; b < Bb; b++) {
            float s = 0.0f;
            for (int ch = 0; ch < NCHUNK; ch++) s += part[((long long)(b * NCHUNK + ch)) * 3 + c];
            acc += sigmoidf_(s / (float)Ls + biases[c]);
        }
        scal[c] = acc / (float)Bb;
    }
}

// ---------------- masked softmax: fp32 in (ld=PLP) -> bf16 padded out ----
__global__ void softmax_kernel(const float* __restrict__ s, bf16* __restrict__ ob)
{
    __shared__ float sh[256];
    int row = blockIdx.x;
    int l = row % Ls;
    int limit = Pp + l + 1;
    const float* p = s + (long long)row * PLP;
    bf16* o = ob + (long long)row * PLP;
    int t = threadIdx.x;

    float mx = -INFINITY;
    for (int i = t; i < limit; i += 256) mx = fmaxf(mx, p[i]);
    sh[t] = mx; __syncthreads();
    for (int st = 128; st > 0; st >>= 1) { if (t < st) sh[t] = fmaxf(sh[t], sh[t + st]); __syncthreads(); }
    mx = sh[0]; __syncthreads();

    float sum = 0.0f;
    for (int i = t; i < limit; i += 256) sum += __expf(p[i] - mx);
    sh[t] = sum; __syncthreads();
    for (int st = 128; st > 0; st >>= 1) { if (t < st) sh[t] += sh[t + st]; __syncthreads(); }
    float inv = 1.0f / sh[0];

    for (int i = t; i < limit; i += 256) o[i] = __float2bfloat16(__expf(p[i] - mx) * inv);
    for (int i = limit + t; i < PLP; i += 256) o[i] = __float2bfloat16(0.0f);
}

// ---------------- final RMSNorm ----------------
__global__ void rmsnorm_kernel(float* __restrict__ out, const float* __restrict__ lnw)
{
    __shared__ float sh[256];
    long long base = (long long)blockIdx.x * Dd;
    int t = threadIdx.x;
    float ss = 0.0f;
    for (int i = t; i < Dd; i += 256) { float v = out[base + i]; ss = fmaf(v, v, ss); }
    sh[t] = ss; __syncthreads();
    for (int s = 128; s > 0; s >>= 1) { if (t < s) sh[t] += sh[t + s]; __syncthreads(); }
    float inv = rsqrtf(sh[0] / (float)Dd + 1e-6f);
    for (int i = t; i < Dd; i += 256) out[base + i] = out[base + i] * inv * lnw[i];
}

// ---------------- host dispatch ----------------
static void gemm(const bf16* A, const bf16* B, float* C, bf16* Cb,
                 int Md, int Nd, int Kd, int lda, int ldb, int ldc,
                 long long sA, long long sB, long long sC, int batch,
                 int epi, const float* aux, long long sAux,
                 const float* bias, float alpha)
{
    static bool attr_set = false;
    if (!attr_set) {
        cudaFuncSetAttribute(bgemm_kernel, cudaFuncAttributeMaxDynamicSharedMemorySize, SMEM_DYN);
        attr_set = true;
    }
    dim3 grid((Nd + BN - 1) / BN, (Md + BM - 1) / BM, batch);
    bgemm_kernel<<<grid, 256, SMEM_DYN>>>(A, B, C, Cb, Md, Nd, Kd, lda, ldb, ldc,
                                          sA, sB, sC, epi, aux, sAux, bias, alpha);
}

static void cvt(const float* in, bf16* out, int n)
{
    cvt_kernel<<<(n / 4 + 255) / 256, 256>>>((const float4*)in, (uint2*)out, n / 4);
}

extern "C" void kernel_launch(void* const* d_in, const int* in_sizes, int n_in,
                              void* d_out, int out_size)
{
    const float* x  = (const float*)d_in[0];
    const float* Wq = (const float*)d_in[1];
    const float* Wk = (const float*)d_in[2];
    const float* Wv = (const float*)d_in[3];

    const float *q_dw, *k_dw, *v_dw, *q_pw, *k_pw, *v_pw;
    if (in_sizes[5] == Mm * Kc) {
        q_dw = (const float*)d_in[4]; k_dw = (const float*)d_in[5]; v_dw = (const float*)d_in[6];
        q_pw = (const float*)d_in[7]; k_pw = (const float*)d_in[8]; v_pw = (const float*)d_in[9];
    } else {
        q_dw = (const float*)d_in[4]; q_pw = (const float*)d_in[5];
        k_dw = (const float*)d_in[6]; k_pw = (const float*)d_in[7];
        v_dw = (const float*)d_in[8]; v_pw = (const float*)d_in[9];
    }
    const float* pk      = (const float*)d_in[10];
    const float* pv      = (const float*)d_in[11];
    const float* mlp_w1  = (const float*)d_in[12];
    const float* mlp_w2  = (const float*)d_in[13];
    const float* eta_w   = (const float*)d_in[14];
    const float* eta_b   = (const float*)d_in[15];
    const float* theta_w = (const float*)d_in[16];
    const float* theta_b = (const float*)d_in[17];
    const float* alpha_w = (const float*)d_in[18];
    const float* alpha_b = (const float*)d_in[19];
    const float* gate_w  = (const float*)d_in[20];
    const float* gate_b  = (const float*)d_in[21];
    const float* out_w   = (const float*)d_in[22];
    const float* ln_w    = (const float*)d_in[23];
    const float* mem_st  = (const float*)d_in[24];
    const float* sur_st  = (const float*)d_in[25];
    float* out = (float*)d_out;

    // fp32 scratch
    float *tmp1, *q, *k, *v, *err, *mom, *ret, *vwp, *scores, *part, *scal;
    cudaGetSymbolAddress((void**)&tmp1, g_tmp1);
    cudaGetSymbolAddress((void**)&q,    g_q);
    cudaGetSymbolAddress((void**)&k,    g_k);
    cudaGetSymbolAddress((void**)&v,    g_v);
    cudaGetSymbolAddress((void**)&err,  g_err);
    cudaGetSymbolAddress((void**)&mom,  g_mom);
    cudaGetSymbolAddress((void**)&ret,  g_ret);
    cudaGetSymbolAddress((void**)&vwp,  g_vwp);
    cudaGetSymbolAddress((void**)&scores, g_scores);
    cudaGetSymbolAddress((void**)&part, g_part);
    cudaGetSymbolAddress((void**)&scal, g_scal);

    // bf16 scratch
    bf16 *xb, *wqb, *wkb, *wvb, *qpwb, *kpwb, *vpwb, *w1b, *w2b, *gwb, *owb;
    bf16 *tmp2b, *qb, *kb, *kTb, *errTb, *memTb, *snapTb, *mlpb, *kwpb, *vwpTb, *scoresb, *retb, *gatb;
    cudaGetSymbolAddress((void**)&xb,   b_x);
    cudaGetSymbolAddress((void**)&wqb,  b_Wq);
    cudaGetSymbolAddress((void**)&wkb,  b_Wk);
    cudaGetSymbolAddress((void**)&wvb,  b_Wv);
    cudaGetSymbolAddress((void**)&qpwb, b_qpw);
    cudaGetSymbolAddress((void**)&kpwb, b_kpw);
    cudaGetSymbolAddress((void**)&vpwb, b_vpw);
    cudaGetSymbolAddress((void**)&w1b,  b_w1);
    cudaGetSymbolAddress((void**)&w2b,  b_w2);
    cudaGetSymbolAddress((void**)&gwb,  b_gw);
    cudaGetSymbolAddress((void**)&owb,  b_ow);
    cudaGetSymbolAddress((void**)&tmp2b, b_tmp2);
    cudaGetSymbolAddress((void**)&qb,   b_q);
    cudaGetSymbolAddress((void**)&kb,   b_k);
    cudaGetSymbolAddress((void**)&kTb,  b_kT);
    cudaGetSymbolAddress((void**)&errTb, b_errT);
    cudaGetSymbolAddress((void**)&memTb, b_memT);
    cudaGetSymbolAddress((void**)&snapTb, b_snapT);
    cudaGetSymbolAddress((void**)&mlpb, b_mlp);
    cudaGetSymbolAddress((void**)&kwpb, b_kwp);
    cudaGetSymbolAddress((void**)&vwpTb, b_vwpT);
    cudaGetSymbolAddress((void**)&scoresb, b_scores);
    cudaGetSymbolAddress((void**)&retb, b_ret);
    cudaGetSymbolAddress((void**)&gatb, b_gat);

    const int EW = Ns * Mm;
    dim3 tb(32, 8);

    // scalars
    pool_partial_kernel<<<Bb * NCHUNK, 256>>>(x, eta_w, theta_w, alpha_w, part);
    pool_final_kernel<<<1, 32>>>(part, eta_b, theta_b, alpha_b, scal);

    // one-time conversions
    cvt(x, xb, Ns * Dd);
    cvt(Wq, wqb, Mm * Dd);  cvt(Wk, wkb, Mm * Dd);  cvt(Wv, wvb, Mm * Dd);
    cvt(q_pw, qpwb, Mm * Mm); cvt(k_pw, kpwb, Mm * Mm); cvt(v_pw, vpwb, Mm * Mm);
    cvt(mlp_w1, w1b, Mm * Mm); cvt(mlp_w2, w2b, Mm * Mm);
    cvt(gate_w, gwb, Mm * Mm); cvt(out_w, owb, Dd * Mm);

    // q branch
    gemm(xb, wqb, tmp1, nullptr, Ns, Mm, Dd, Dd, Dd, Mm, 0, 0, 0, 1, EPI_NONE, nullptr, 0, nullptr, 0.f);
    dwconv_kernel<<<EW / 256, 256>>>(tmp1, q_dw, tmp2b);
    gemm(tmp2b, qpwb, q, nullptr, Ns, Mm, Mm, Mm, Mm, Mm, 0, 0, 0, 1, EPI_SILU, nullptr, 0, nullptr, 0.f);
    // k branch
    gemm(xb, wkb, tmp1, nullptr, Ns, Mm, Dd, Dd, Dd, Mm, 0, 0, 0, 1, EPI_NONE, nullptr, 0, nullptr, 0.f);
    dwconv_kernel<<<EW / 256, 256>>>(tmp1, k_dw, tmp2b);
    gemm(tmp2b, kpwb, k, nullptr, Ns, Mm, Mm, Mm, Mm, Mm, 0, 0, 0, 1, EPI_SILU, nullptr, 0, nullptr, 0.f);
    // v branch
    gemm(xb, wvb, tmp1, nullptr, Ns, Mm, Dd, Dd, Dd, Mm, 0, 0, 0, 1, EPI_NONE, nullptr, 0, nullptr, 0.f);
    dwconv_kernel<<<EW / 256, 256>>>(tmp1, v_dw, tmp2b);
    gemm(tmp2b, vpwb, v, nullptr, Ns, Mm, Mm, Mm, Mm, Mm, 0, 0, 0, 1, EPI_SILU, nullptr, 0, nullptr, 0.f);

    l2n_kernel<<<Ns, 256>>>(q, qb, Mm);
    l2n_kernel<<<Ns, 256>>>(k, kb, Mm);

    build_wp_kernel<<<Bb * PL, 256>>>(pk, pv, k, v, kwpb, vwp);

    // err = v - k @ mem
    transpose_bf_kernel<<<dim3(Mm / 32, Mm / 32, 1), tb>>>(mem_st, memTb, Mm, Mm, Mm, 0, 0);
    gemm(kb, memTb, err, nullptr, Ns, Mm, Mm, Mm, Mm, Mm, 0, 0, 0, 1, EPI_RSUB, v, 0, nullptr, 0.f);

    // momentary = k^T @ err / Ns
    transpose_bf_kernel<<<dim3(Mm / 32, Ns / 32, 1), tb>>>(k, kTb, Ns, Mm, Ns, 0, 0);
    transpose_bf_kernel<<<dim3(Mm / 32, Ns / 32, 1), tb>>>(err, errTb, Ns, Mm, Ns, 0, 0);
    gemm(kTb, errTb, mom, nullptr, Mm, Mm, Ns, Ns, Ns, Mm, 0, 0, 0, 1, EPI_SCALE, nullptr, 0, nullptr, 1.0f / (float)Ns);

    snapT_kernel<<<dim3(Mm / 32, Mm / 32), tb>>>(mem_st, sur_st, mom, scal, snapTb);

    // retrieved = q @ snap + silu(q @ w1^T) @ w2^T
    gemm(qb, snapTb, ret, nullptr, Ns, Mm, Mm, Mm, Mm, Mm, 0, 0, 0, 1, EPI_NONE, nullptr, 0, nullptr, 0.f);
    gemm(qb, w1b, nullptr, mlpb, Ns, Mm, Mm, Mm, Mm, Mm, 0, 0, 0, 1, EPI_SILU, nullptr, 0, nullptr, 0.f);
    gemm(mlpb, w2b, ret, nullptr, Ns, Mm, Mm, Mm, Mm, Mm, 0, 0, 0, 1, EPI_ADD, ret, 0, nullptr, 0.f);

    // attention: scores (fp32, ld=PLP) -> softmax -> bf16 padded
    gemm(qb, kwpb, scores, nullptr, Ls, PL, Mm, Mm, Mm, PLP,
         (long long)Ls * Mm, (long long)PL * Mm, (long long)Ls * PLP, Bb,
         EPI_SCALE, nullptr, 0, nullptr, rsqrtf((float)Mm));
    softmax_kernel<<<Bb * Ls, 256>>>(scores, scoresb);
    transpose_bf_kernel<<<dim3(Mm / 32, PLP / 32, Bb), tb>>>(vwp, vwpTb, PL, Mm, PLP,
         (long long)PL * Mm, (long long)Mm * PLP);
    gemm(scoresb, vwpTb, ret, retb, Ls, Mm, PLP, PLP, PLP, Mm,
         (long long)Ls * PLP, (long long)Mm * PLP, (long long)Ls * Mm, Bb,
         EPI_ADD, ret, (long long)Ls * Mm, nullptr, 0.f);

    // gate + output + RMSNorm
    gemm(retb, gwb, nullptr, gatb, Ns, Mm, Mm, Mm, Mm, Mm, 0, 0, 0, 1, EPI_GATE, ret, 0, gate_b, 0.f);
    gemm(gatb, owb, out, nullptr, Ns, Dd, Mm, Mm, Mm, Dd, 0, 0, 0, 1, EPI_ADD, x, 0, nullptr, 0.f);
    rmsnorm_kernel<<<Ns, 256>>>(out, ln_w);
}

// round 6
// speedup vs baseline: 7.3523x; 1.1278x over previous
#include <cuda_runtime.h>
#include <cuda_bf16.h>
#include <math.h>
#include <stdint.h>

// ---------------- problem dims (fixed) ----------------
#define Bb 2
#define Ls 1024
#define Dd 2048
#define Mm 2048
#define Pp 8
#define Kc 4
#define Ns (Bb*Ls)
#define PL (Pp+Ls)
#define PLP 1056
#define NCHUNK 64

typedef __nv_bfloat16 bf16;

// ---------------- fp32 scratch ----------------
__device__ float g_q[Ns*Mm];
__device__ float g_k[Ns*Mm];
__device__ float g_v[Ns*Mm];
__device__ float g_err[Ns*Mm];
__device__ float g_mom[Mm*Mm];
__device__ float g_ret[Ns*Mm];
__device__ float g_vwp[Bb*PL*Mm];
__device__ float g_scores[Bb*Ls*PLP];
__device__ float g_part[Bb*NCHUNK*3];
__device__ float g_scal[3];

// ---------------- bf16 scratch ----------------
__device__ bf16 b_x[Ns*Dd];
__device__ bf16 b_Wq[Mm*Dd];
__device__ bf16 b_Wk[Mm*Dd];
__device__ bf16 b_Wv[Mm*Dd];
__device__ bf16 b_qpw[Mm*Mm];
__device__ bf16 b_kpw[Mm*Mm];
__device__ bf16 b_vpw[Mm*Mm];
__device__ bf16 b_w1[Mm*Mm];
__device__ bf16 b_w2[Mm*Mm];
__device__ bf16 b_gw[Mm*Mm];
__device__ bf16 b_ow[Dd*Mm];
__device__ bf16 b_proj[Ns*Mm];
__device__ bf16 b_dw[Ns*Mm];
__device__ bf16 b_q[Ns*Mm];
__device__ bf16 b_k[Ns*Mm];
__device__ bf16 b_kT[Mm*Ns];
__device__ bf16 b_errT[Mm*Ns];
__device__ bf16 b_memT[Mm*Mm];
__device__ bf16 b_snapT[Mm*Mm];
__device__ bf16 b_mlp[Ns*Mm];
__device__ bf16 b_kwp[Bb*PL*Mm];
__device__ bf16 b_vwpT[Bb*Mm*PLP];
__device__ bf16 b_scores[Bb*Ls*PLP];
__device__ bf16 b_ret[Ns*Mm];
__device__ bf16 b_gat[Ns*Mm];

// ---------------- epilogues ----------------
#define EPI_NONE  0
#define EPI_SILU  1
#define EPI_RSUB  2
#define EPI_SCALE 3
#define EPI_ADD   4
#define EPI_GATE  5

__device__ __forceinline__ float sigmoidf_(float x) { return 1.0f / (1.0f + __expf(-x)); }

__device__ __forceinline__ uint32_t pbf2(float lo, float hi) {
    uint32_t r;
    asm("cvt.rn.bf16x2.f32 %0, %1, %2;" : "=r"(r) : "f"(hi), "f"(lo));
    return r;
}

__device__ __forceinline__ uint32_t smem_u32(const void* p) {
    uint32_t a;
    asm("{ .reg .u64 t; cvta.to.shared.u64 t, %1; cvt.u32.u64 %0, t; }" : "=r"(a) : "l"(p));
    return a;
}

__device__ __forceinline__ void mma_bf16(float* d, const uint32_t* a, const uint32_t* b) {
    asm volatile(
        "mma.sync.aligned.m16n8k16.row.col.f32.bf16.bf16.f32 "
        "{%0,%1,%2,%3},{%4,%5,%6,%7},{%8,%9},{%0,%1,%2,%3};\n"
        : "+f"(d[0]), "+f"(d[1]), "+f"(d[2]), "+f"(d[3])
        : "r"(a[0]), "r"(a[1]), "r"(a[2]), "r"(a[3]), "r"(b[0]), "r"(b[1]));
}

__device__ __forceinline__ void cp16(uint32_t dst, const void* src, uint32_t sz) {
    asm volatile("cp.async.cg.shared.global [%0], [%1], 16, %2;"
                 :: "r"(dst), "l"(src), "r"(sz));
}

#define LDSM4(r0, r1, r2, r3, addr) \
    asm volatile("ldmatrix.sync.aligned.m8n8.x4.shared.b16 {%0,%1,%2,%3}, [%4];" \
                 : "=r"(r0), "=r"(r1), "=r"(r2), "=r"(r3) : "r"(addr))

// ---------------- bf16 cp.async pipelined GEMM (NT) ----------------
#define BM 128
#define BN 128
#define BK 32
#define SKB 40
#define STAGES 4
#define TILE_ELEMS (BM * SKB)
#define SMEM_DYN (STAGES * 2 * TILE_ELEMS * 2)

__global__ void __launch_bounds__(256, 2) bgemm_kernel(
    const bf16* __restrict__ A, const bf16* __restrict__ B,
    float* __restrict__ C, bf16* __restrict__ Cb,
    int Md, int Nd, int Kd, int lda, int ldb, int ldc,
    long long strA, long long strB, long long strC,
    int epi, const float* __restrict__ aux, long long strAux,
    const float* __restrict__ bias, float alpha)
{
    extern __shared__ bf16 smp[];
    bf16* Asb = smp;
    bf16* Bsb = smp + STAGES * TILE_ELEMS;

    const int bz = blockIdx.z;
    A += (long long)bz * strA;
    B += (long long)bz * strB;
    if (C)   C  += (long long)bz * strC;
    if (Cb)  Cb += (long long)bz * strC;
    if (aux) aux += (long long)bz * strAux;

    const int t    = threadIdx.x;
    const int lane = t & 31;
    const int warp = t >> 5;
    const int wm   = warp & 3;
    const int wn   = warp >> 2;
    const int grp  = lane >> 2;
    const int qid  = lane & 3;
    const int m0   = blockIdx.y * BM;
    const int n0   = blockIdx.x * BN;

    float acc[2][8][4];
#pragma unroll
    for (int mi = 0; mi < 2; mi++)
#pragma unroll
        for (int ni = 0; ni < 8; ni++)
#pragma unroll
            for (int c = 0; c < 4; c++) acc[mi][ni][c] = 0.0f;

    const int nk = Kd / BK;

    const int row0 = t >> 2;
    const int ch   = t & 3;

    auto loadTile = [&](int stage, int k0) {
        uint32_t abase = smem_u32(&Asb[stage * TILE_ELEMS]);
        uint32_t bbase = smem_u32(&Bsb[stage * TILE_ELEMS]);
#pragma unroll
        for (int i = 0; i < 2; i++) {
            int m = row0 + i * 64;
            cp16(abase + (m * SKB + ch * 8) * 2,
                 A + (long long)(m0 + m) * lda + k0 + ch * 8, 16u);
            int gn = n0 + m;
            bool ok = gn < Nd;
            cp16(bbase + (m * SKB + ch * 8) * 2,
                 B + (ok ? (long long)gn * ldb + k0 + ch * 8 : 0ll), ok ? 16u : 0u);
        }
        asm volatile("cp.async.commit_group;" ::: "memory");
    };

    loadTile(0, 0);
    loadTile(1, BK);
    loadTile(2, 2 * BK);

    // ldmatrix lane-address components (element offsets within a tile)
    const uint32_t asb0 = smem_u32(Asb);
    const uint32_t bsb0 = smem_u32(Bsb);
    // A: lanes 0-7 rows 0-7 @k, 8-15 rows 8-15 @k, 16-23 rows 0-7 @k+8, 24-31 rows 8-15 @k+8
    const int a_row   = wm * 32 + (lane & 15);
    const int a_khalf = (lane >> 4) * 8;
    // B pair-of-n-tiles: lanes 0-7 tile j rows @k, 8-15 tile j rows @k+8,
    //                    16-23 tile j+1 rows @k, 24-31 tile j+1 rows @k+8
    const int b_row   = wn * 64 + (lane >> 4) * 8 + (lane & 7);
    const int b_khalf = ((lane >> 3) & 1) * 8;

    for (int kt = 0; kt < nk; kt++) {
        asm volatile("cp.async.wait_group 2;" ::: "memory");
        __syncthreads();

        if (kt + 3 < nk) loadTile((kt + 3) & 3, (kt + 3) * BK);
        else asm volatile("cp.async.commit_group;" ::: "memory");

        const uint32_t soff = (kt & 3) * TILE_ELEMS;

#pragma unroll
        for (int kk = 0; kk < BK; kk += 16) {
            uint32_t af[2][4], bf[8][2];
#pragma unroll
            for (int mi = 0; mi < 2; mi++) {
                uint32_t addr = asb0 + (soff + (a_row + mi * 16) * SKB + kk + a_khalf) * 2;
                LDSM4(af[mi][0], af[mi][1], af[mi][2], af[mi][3], addr);
            }
#pragma unroll
            for (int nj = 0; nj < 8; nj += 2) {
                uint32_t addr = bsb0 + (soff + (b_row + nj * 8) * SKB + kk + b_khalf) * 2;
                LDSM4(bf[nj][0], bf[nj][1], bf[nj + 1][0], bf[nj + 1][1], addr);
            }
#pragma unroll
            for (int mi = 0; mi < 2; mi++)
#pragma unroll
                for (int ni = 0; ni < 8; ni++)
                    mma_bf16(acc[mi][ni], af[mi], bf[ni]);
        }
    }

    // ---- epilogue ----
#pragma unroll
    for (int mi = 0; mi < 2; mi++) {
#pragma unroll
        for (int half = 0; half < 2; half++) {
            int row = m0 + wm * 32 + mi * 16 + grp + half * 8;
#pragma unroll
            for (int ni = 0; ni < 8; ni++) {
                int col = n0 + wn * 64 + ni * 8 + qid * 2;
                if (col + 1 >= Nd) continue;
                float v0 = acc[mi][ni][half * 2 + 0];
                float v1 = acc[mi][ni][half * 2 + 1];
                long long idx = (long long)row * ldc + col;
                switch (epi) {
                    case EPI_SILU:
                        v0 = v0 * sigmoidf_(v0); v1 = v1 * sigmoidf_(v1); break;
                    case EPI_RSUB: {
                        float2 a2 = *(const float2*)(aux + idx);
                        v0 = a2.x - v0; v1 = a2.y - v1; break; }
                    case EPI_SCALE:
                        v0 *= alpha; v1 *= alpha; break;
                    case EPI_ADD: {
                        float2 a2 = *(const float2*)(aux + idx);
                        v0 += a2.x; v1 += a2.y; break; }
                    case EPI_GATE: {
                        float2 a2 = *(const float2*)(aux + idx);
                        v0 = sigmoidf_(v0 + bias[col]) * a2.x;
                        v1 = sigmoidf_(v1 + bias[col + 1]) * a2.y; break; }
                    default: break;
                }
                if (C) { float2 o; o.x = v0; o.y = v1; *(float2*)(C + idx) = o; }
                if (Cb) *(uint32_t*)(Cb + idx) = pbf2(v0, v1);
            }
        }
    }
}

// ---------------- f32 -> bf16 convert (grid-stride, 4x/thread) ------
__global__ void cvt_kernel(const float4* __restrict__ in, uint2* __restrict__ out, int n4)
{
    int stride = gridDim.x * blockDim.x;
    for (int i = blockIdx.x * blockDim.x + threadIdx.x; i < n4; i += stride) {
        float4 x = in[i];
        uint2 o; o.x = pbf2(x.x, x.y); o.y = pbf2(x.z, x.w);
        out[i] = o;
    }
}

// ---------------- tiled transpose f32 -> bf16 ----------------
__global__ void transpose_bf_kernel(const float* __restrict__ in, bf16* __restrict__ out,
                                    int R, int Cc, int ldo, long long sIn, long long sOut)
{
    __shared__ float tile[32][33];
    int z = blockIdx.z;
    in  += (long long)z * sIn;
    out += (long long)z * sOut;
    int c0 = blockIdx.x * 32, r0 = blockIdx.y * 32;
    int tx = threadIdx.x, ty = threadIdx.y;
#pragma unroll
    for (int i = ty; i < 32; i += 8) {
        int r = r0 + i, c = c0 + tx;
        tile[i][tx] = (r < R && c < Cc) ? in[(long long)r * Cc + c] : 0.0f;
    }
    __syncthreads();
#pragma unroll
    for (int i = ty; i < 32; i += 8) {
        int c = c0 + i, r = r0 + tx;
        if (c < Cc && r < ldo) out[(long long)c * ldo + r] = __float2bfloat16(tile[tx][i]);
    }
}

// ---------------- snapT -> bf16 ----------------
__global__ void snapT_kernel(const float* __restrict__ mem, const float* __restrict__ sur,
                             const float* __restrict__ mom, const float* __restrict__ scal,
                             bf16* __restrict__ snapT)
{
    __shared__ float tile[32][33];
    int c0 = blockIdx.x * 32, r0 = blockIdx.y * 32;
    int tx = threadIdx.x, ty = threadIdx.y;
    float eta = scal[0], theta = scal[1], alpha = scal[2];
#pragma unroll
    for (int i = ty; i < 32; i += 8) {
        long long idx = (long long)(r0 + i) * Mm + c0 + tx;
        tile[i][tx] = (1.f - alpha) * mem[idx] + eta * sur[idx] + theta * mom[idx];
    }
    __syncthreads();
#pragma unroll
    for (int i = ty; i < 32; i += 8)
        snapT[(long long)(c0 + i) * Mm + r0 + tx] = __float2bfloat16(tile[tx][i]);
}

// ---------------- depthwise causal conv (bf16 in/out) ----------------
__global__ void dwconv_kernel(const bf16* __restrict__ in, const float* __restrict__ w,
                              bf16* __restrict__ out)
{
    long long idx = (long long)blockIdx.x * blockDim.x + threadIdx.x;
    if (idx >= (long long)Ns * Mm) return;
    int c = (int)(idx % Mm);
    long long bl = idx / Mm;
    int l = (int)(bl % Ls);
    long long b = bl / Ls;
    float s = 0.0f;
#pragma unroll
    for (int j = 0; j < Kc; j++) {
        int li = l - (Kc - 1) + j;
        if (li >= 0)
            s = fmaf(w[c * Kc + j], __bfloat162float(in[((long long)b * Ls + li) * Mm + c]), s);
    }
    out[idx] = __float2bfloat16(s);
}

// ---------------- row L2 normalize ----------------
__global__ void l2n_kernel(float* __restrict__ p, bf16* __restrict__ pb, int cols)
{
    __shared__ float sh[256];
    long long base = (long long)blockIdx.x * cols;
    int t = threadIdx.x;
    float ss = 0.0f;
    for (int i = t; i < cols; i += 256) { float v = p[base + i]; ss = fmaf(v, v, ss); }
    sh[t] = ss; __syncthreads();
    for (int s = 128; s > 0; s >>= 1) { if (t < s) sh[t] += sh[t + s]; __syncthreads(); }
    float inv = 1.0f / (sqrtf(sh[0]) + 1e-6f);
    for (int i = t; i < cols; i += 256) {
        float v = p[base + i] * inv;
        p[base + i] = v;
        pb[base + i] = __float2bfloat16(v);
    }
}

// ---------------- build kwp (bf16) / vwp (fp32) ----------------
__global__ void build_wp_kernel(const float* __restrict__ pk, const float* __restrict__ pv,
                                const float* __restrict__ k, const float* __restrict__ v,
                                bf16* __restrict__ kwp, float* __restrict__ vwp)
{
    __shared__ float sh[256];
    int r = blockIdx.x;
    int b = r / PL;
    int p = r % PL;
    int t = threadIdx.x;
    long long dst = (long long)r * Mm;
    if (p < Pp) {
        float ss = 0.0f;
        for (int i = t; i < Mm; i += 256) { float x = pk[p * Mm + i]; ss = fmaf(x, x, ss); }
        sh[t] = ss; __syncthreads();
        for (int s = 128; s > 0; s >>= 1) { if (t < s) sh[t] += sh[t + s]; __syncthreads(); }
        float inv = 1.0f / (sqrtf(sh[0]) + 1e-6f);
        for (int i = t; i < Mm; i += 256) {
            kwp[dst + i] = __float2bfloat16(pk[p * Mm + i] * inv);
            vwp[dst + i] = pv[p * Mm + i];
        }
    } else {
        long long src = ((long long)b * Ls + (p - Pp)) * Mm;
        for (int i = t; i < Mm; i += 256) {
            kwp[dst + i] = __float2bfloat16(k[src + i]);
            vwp[dst + i] = v[src + i];
        }
    }
}

// ---------------- eta/theta/alpha ----------------
__global__ void pool_partial_kernel(const float* __restrict__ x,
                                    const float* __restrict__ ew, const float* __restrict__ tw,
                                    const float* __restrict__ aw, float* __restrict__ part)
{
    __shared__ float sh[256];
    int blk = blockIdx.x;
    int b  = blk / NCHUNK;
    int ch = blk % NCHUNK;
    int t = threadIdx.x;
    const int span = (Ls * Dd) / NCHUNK;
    long long base = (long long)b * Ls * Dd;
    float s0 = 0.0f, s1 = 0.0f, s2 = 0.0f;
    for (int i = ch * span + t; i < (ch + 1) * span; i += 256) {
        float xv = x[base + i];
        int d = i & (Dd - 1);
        s0 = fmaf(xv, ew[d], s0);
        s1 = fmaf(xv, tw[d], s1);
        s2 = fmaf(xv, aw[d], s2);
    }
    float vals[3] = {s0, s1, s2};
#pragma unroll
    for (int c = 0; c < 3; c++) {
        sh[t] = vals[c]; __syncthreads();
        for (int s = 128; s > 0; s >>= 1) { if (t < s) sh[t] += sh[t + s]; __syncthreads(); }
        if (t == 0) part[(long long)blk * 3 + c] = sh[0];
        __syncthreads();
    }
}

__global__ void pool_final_kernel(const float* __restrict__ part,
                                  const float* __restrict__ eb, const float* __restrict__ tb,
                                  const float* __restrict__ ab, float* __restrict__ scal)
{
    if (threadIdx.x != 0) return;
    float biases[3] = {eb[0], tb[0], ab[0]};
    for (int c = 0; c < 3; c++) {
        float acc = 0.0f;
        for (int b = 0; b < Bb; b++) {
            float s = 0.0f;
            for (int ch = 0; ch < NCHUNK; ch++) s += part[((long long)(b * NCHUNK + ch)) * 3 + c];
            acc += sigmoidf_(s / (float)Ls + biases[c]);
        }
        scal[c] = acc / (float)Bb;
    }
}

// ---------------- masked softmax ----------------
__global__ void softmax_kernel(const float* __restrict__ s, bf16* __restrict__ ob)
{
    __shared__ float sh[256];
    int row = blockIdx.x;
    int l = row % Ls;
    int limit = Pp + l + 1;
    const float* p = s + (long long)row * PLP;
    bf16* o = ob + (long long)row * PLP;
    int t = threadIdx.x;

    float mx = -INFINITY;
    for (int i = t; i < limit; i += 256) mx = fmaxf(mx, p[i]);
    sh[t] = mx; __syncthreads();
    for (int st = 128; st > 0; st >>= 1) { if (t < st) sh[t] = fmaxf(sh[t], sh[t + st]); __syncthreads(); }
    mx = sh[0]; __syncthreads();

    float sum = 0.0f;
    for (int i = t; i < limit; i += 256) sum += __expf(p[i] - mx);
    sh[t] = sum; __syncthreads();
    for (int st = 128; st > 0; st >>= 1) { if (t < st) sh[t] += sh[t + st]; __syncthreads(); }
    float inv = 1.0f / sh[0];

    for (int i = t; i < limit; i += 256) o[i] = __float2bfloat16(__expf(p[i] - mx) * inv);
    for (int i = limit + t; i < PLP; i += 256) o[i] = __float2bfloat16(0.0f);
}

// ---------------- final RMSNorm ----------------
__global__ void rmsnorm_kernel(float* __restrict__ out, const float* __restrict__ lnw)
{
    __shared__ float sh[256];
    long long base = (long long)blockIdx.x * Dd;
    int t = threadIdx.x;
    float ss = 0.0f;
    for (int i = t; i < Dd; i += 256) { float v = out[base + i]; ss = fmaf(v, v, ss); }
    sh[t] = ss; __syncthreads();
    for (int s = 128; s > 0; s >>= 1) { if (t < s) sh[t] += sh[t + s]; __syncthreads(); }
    float inv = rsqrtf(sh[0] / (float)Dd + 1e-6f);
    for (int i = t; i < Dd; i += 256) out[base + i] = out[base + i] * inv * lnw[i];
}

// ---------------- host dispatch ----------------
static void gemm(const bf16* A, const bf16* B, float* C, bf16* Cb,
                 int Md, int Nd, int Kd, int lda, int ldb, int ldc,
                 long long sA, long long sB, long long sC, int batch,
                 int epi, const float* aux, long long sAux,
                 const float* bias, float alpha)
{
    static bool attr_set = false;
    if (!attr_set) {
        cudaFuncSetAttribute(bgemm_kernel, cudaFuncAttributeMaxDynamicSharedMemorySize, SMEM_DYN);
        attr_set = true;
    }
    dim3 grid((Nd + BN - 1) / BN, (Md + BM - 1) / BM, batch);
    bgemm_kernel<<<grid, 256, SMEM_DYN>>>(A, B, C, Cb, Md, Nd, Kd, lda, ldb, ldc,
                                          sA, sB, sC, epi, aux, sAux, bias, alpha);
}

static void cvt(const float* in, bf16* out, int n)
{
    int n4 = n / 4;
    int blocks = (n4 + 1023) / 1024;
    cvt_kernel<<<blocks, 256>>>((const float4*)in, (uint2*)out, n4);
}

extern "C" void kernel_launch(void* const* d_in, const int* in_sizes, int n_in,
                              void* d_out, int out_size)
{
    const float* x  = (const float*)d_in[0];
    const float* Wq = (const float*)d_in[1];
    const float* Wk = (const float*)d_in[2];
    const float* Wv = (const float*)d_in[3];

    const float *q_dw, *k_dw, *v_dw, *q_pw, *k_pw, *v_pw;
    if (in_sizes[5] == Mm * Kc) {
        q_dw = (const float*)d_in[4]; k_dw = (const float*)d_in[5]; v_dw = (const float*)d_in[6];
        q_pw = (const float*)d_in[7]; k_pw = (const float*)d_in[8]; v_pw = (const float*)d_in[9];
    } else {
        q_dw = (const float*)d_in[4]; q_pw = (const float*)d_in[5];
        k_dw = (const float*)d_in[6]; k_pw = (const float*)d_in[7];
        v_dw = (const float*)d_in[8]; v_pw = (const float*)d_in[9];
    }
    const float* pk      = (const float*)d_in[10];
    const float* pv      = (const float*)d_in[11];
    const float* mlp_w1  = (const float*)d_in[12];
    const float* mlp_w2  = (const float*)d_in[13];
    const float* eta_w   = (const float*)d_in[14];
    const float* eta_b   = (const float*)d_in[15];
    const float* theta_w = (const float*)d_in[16];
    const float* theta_b = (const float*)d_in[17];
    const float* alpha_w = (const float*)d_in[18];
    const float* alpha_b = (const float*)d_in[19];
    const float* gate_w  = (const float*)d_in[20];
    const float* gate_b  = (const float*)d_in[21];
    const float* out_w   = (const float*)d_in[22];
    const float* ln_w    = (const float*)d_in[23];
    const float* mem_st  = (const float*)d_in[24];
    const float* sur_st  = (const float*)d_in[25];
    float* out = (float*)d_out;

    float *q, *k, *v, *err, *mom, *ret, *vwp, *scores, *part, *scal;
    cudaGetSymbolAddress((void**)&q,    g_q);
    cudaGetSymbolAddress((void**)&k,    g_k);
    cudaGetSymbolAddress((void**)&v,    g_v);
    cudaGetSymbolAddress((void**)&err,  g_err);
    cudaGetSymbolAddress((void**)&mom,  g_mom);
    cudaGetSymbolAddress((void**)&ret,  g_ret);
    cudaGetSymbolAddress((void**)&vwp,  g_vwp);
    cudaGetSymbolAddress((void**)&scores, g_scores);
    cudaGetSymbolAddress((void**)&part, g_part);
    cudaGetSymbolAddress((void**)&scal, g_scal);

    bf16 *xb, *wqb, *wkb, *wvb, *qpwb, *kpwb, *vpwb, *w1b, *w2b, *gwb, *owb;
    bf16 *projb, *dwb, *qb, *kb, *kTb, *errTb, *memTb, *snapTb, *mlpb, *kwpb, *vwpTb, *scoresb, *retb, *gatb;
    cudaGetSymbolAddress((void**)&xb,   b_x);
    cudaGetSymbolAddress((void**)&wqb,  b_Wq);
    cudaGetSymbolAddress((void**)&wkb,  b_Wk);
    cudaGetSymbolAddress((void**)&wvb,  b_Wv);
    cudaGetSymbolAddress((void**)&qpwb, b_qpw);
    cudaGetSymbolAddress((void**)&kpwb, b_kpw);
    cudaGetSymbolAddress((void**)&vpwb, b_vpw);
    cudaGetSymbolAddress((void**)&w1b,  b_w1);
    cudaGetSymbolAddress((void**)&w2b,  b_w2);
    cudaGetSymbolAddress((void**)&gwb,  b_gw);
    cudaGetSymbolAddress((void**)&owb,  b_ow);
    cudaGetSymbolAddress((void**)&projb, b_proj);
    cudaGetSymbolAddress((void**)&dwb,  b_dw);
    cudaGetSymbolAddress((void**)&qb,   b_q);
    cudaGetSymbolAddress((void**)&kb,   b_k);
    cudaGetSymbolAddress((void**)&kTb,  b_kT);
    cudaGetSymbolAddress((void**)&errTb, b_errT);
    cudaGetSymbolAddress((void**)&memTb, b_memT);
    cudaGetSymbolAddress((void**)&snapTb, b_snapT);
    cudaGetSymbolAddress((void**)&mlpb, b_mlp);
    cudaGetSymbolAddress((void**)&kwpb, b_kwp);
    cudaGetSymbolAddress((void**)&vwpTb, b_vwpT);
    cudaGetSymbolAddress((void**)&scoresb, b_scores);
    cudaGetSymbolAddress((void**)&retb, b_ret);
    cudaGetSymbolAddress((void**)&gatb, b_gat);

    const int EW = Ns * Mm;
    dim3 tb(32, 8);

    pool_partial_kernel<<<Bb * NCHUNK, 256>>>(x, eta_w, theta_w, alpha_w, part);
    pool_final_kernel<<<1, 32>>>(part, eta_b, theta_b, alpha_b, scal);

    cvt(x, xb, Ns * Dd);
    cvt(Wq, wqb, Mm * Dd);  cvt(Wk, wkb, Mm * Dd);  cvt(Wv, wvb, Mm * Dd);
    cvt(q_pw, qpwb, Mm * Mm); cvt(k_pw, kpwb, Mm * Mm); cvt(v_pw, vpwb, Mm * Mm);
    cvt(mlp_w1, w1b, Mm * Mm); cvt(mlp_w2, w2b, Mm * Mm);
    cvt(gate_w, gwb, Mm * Mm); cvt(out_w, owb, Dd * Mm);

    // q branch (bf16 intermediates)
    gemm(xb, wqb, nullptr, projb, Ns, Mm, Dd, Dd, Dd, Mm, 0, 0, 0, 1, EPI_NONE, nullptr, 0, nullptr, 0.f);
    dwconv_kernel<<<EW / 256, 256>>>(projb, q_dw, dwb);
    gemm(dwb, qpwb, q, nullptr, Ns, Mm, Mm, Mm, Mm, Mm, 0, 0, 0, 1, EPI_SILU, nullptr, 0, nullptr, 0.f);
    // k branch
    gemm(xb, wkb, nullptr, projb, Ns, Mm, Dd, Dd, Dd, Mm, 0, 0, 0, 1, EPI_NONE, nullptr, 0, nullptr, 0.f);
    dwconv_kernel<<<EW / 256, 256>>>(projb, k_dw, dwb);
    gemm(dwb, kpwb, k, nullptr, Ns, Mm, Mm, Mm, Mm, Mm, 0, 0, 0, 1, EPI_SILU, nullptr, 0, nullptr, 0.f);
    // v branch
    gemm(xb, wvb, nullptr, projb, Ns, Mm, Dd, Dd, Dd, Mm, 0, 0, 0, 1, EPI_NONE, nullptr, 0, nullptr, 0.f);
    dwconv_kernel<<<EW / 256, 256>>>(projb, v_dw, dwb);
    gemm(dwb, vpwb, v, nullptr, Ns, Mm, Mm, Mm, Mm, Mm, 0, 0, 0, 1, EPI_SILU, nullptr, 0, nullptr, 0.f);

    l2n_kernel<<<Ns, 256>>>(q, qb, Mm);
    l2n_kernel<<<Ns, 256>>>(k, kb, Mm);

    build_wp_kernel<<<Bb * PL, 256>>>(pk, pv, k, v, kwpb, vwp);

    transpose_bf_kernel<<<dim3(Mm / 32, Mm / 32, 1), tb>>>(mem_st, memTb, Mm, Mm, Mm, 0, 0);
    gemm(kb, memTb, err, nullptr, Ns, Mm, Mm, Mm, Mm, Mm, 0, 0, 0, 1, EPI_RSUB, v, 0, nullptr, 0.f);

    transpose_bf_kernel<<<dim3(Mm / 32, Ns / 32, 1), tb>>>(k, kTb, Ns, Mm, Ns, 0, 0);
    transpose_bf_kernel<<<dim3(Mm / 32, Ns / 32, 1), tb>>>(err, errTb, Ns, Mm, Ns, 0, 0);
    gemm(kTb, errTb, mom, nullptr, Mm, Mm, Ns, Ns, Ns, Mm, 0, 0, 0, 1, EPI_SCALE, nullptr, 0, nullptr, 1.0f / (float)Ns);

    snapT_kernel<<<dim3(Mm / 32, Mm / 32), tb>>>(mem_st, sur_st, mom, scal, snapTb);

    gemm(qb, snapTb, ret, nullptr, Ns, Mm, Mm, Mm, Mm, Mm, 0, 0, 0, 1, EPI_NONE, nullptr, 0, nullptr, 0.f);
    gemm(qb, w1b, nullptr, mlpb, Ns, Mm, Mm, Mm, Mm, Mm, 0, 0, 0, 1, EPI_SILU, nullptr, 0, nullptr, 0.f);
    gemm(mlpb, w2b, ret, nullptr, Ns, Mm, Mm, Mm, Mm, Mm, 0, 0, 0, 1, EPI_ADD, ret, 0, nullptr, 0.f);

    gemm(qb, kwpb, scores, nullptr, Ls, PL, Mm, Mm, Mm, PLP,
         (long long)Ls * Mm, (long long)PL * Mm, (long long)Ls * PLP, Bb,
         EPI_SCALE, nullptr, 0, nullptr, rsqrtf((float)Mm));
    softmax_kernel<<<Bb * Ls, 256>>>(scores, scoresb);
    transpose_bf_kernel<<<dim3(Mm / 32, PLP / 32, Bb), tb>>>(vwp, vwpTb, PL, Mm, PLP,
         (long long)PL * Mm, (long long)Mm * PLP);
    gemm(scoresb, vwpTb, ret, retb, Ls, Mm, PLP, PLP, PLP, Mm,
         (long long)Ls * PLP, (long long)Mm * PLP, (long long)Ls * Mm, Bb,
         EPI_ADD, ret, (long long)Ls * Mm, nullptr, 0.f);

    gemm(retb, gwb, nullptr, gatb, Ns, Mm, Mm, Mm, Mm, Mm, 0, 0, 0, 1, EPI_GATE, ret, 0, gate_b, 0.f);
    gemm(gatb, owb, out, nullptr, Ns, Dd, Mm, Mm, Mm, Dd, 0, 0, 0, 1, EPI_ADD, x, 0, nullptr, 0.f);
    rmsnorm_kernel<<<Ns, 256>>>(out, ln_w);
}